// round 2
// baseline (speedup 1.0000x reference)
#include <cuda_runtime.h>
#include <math.h>

// ---------------------------------------------------------------------------
// Scratch (allocation-free rule: __device__ globals)
// ---------------------------------------------------------------------------
__device__ float g_Q [(size_t)4096 * 1024];
__device__ float g_K [(size_t)4096 * 1024];
__device__ float g_V [(size_t)4096 * 1024];
__device__ float g_Y [(size_t)4096 * 1024];
__device__ float g_FF[(size_t)4096 * 4096];

typedef unsigned long long u64;

// ---- packed f32x2 helpers (sm_100+; ptxas never auto-fuses these) ---------
__device__ __forceinline__ u64 pack2(float lo, float hi) {
    u64 r; asm("mov.b64 %0, {%1, %2};" : "=l"(r) : "f"(lo), "f"(hi)); return r;
}
__device__ __forceinline__ u64 splat2(float v) { return pack2(v, v); }
__device__ __forceinline__ float2 unpack2(u64 v) {
    float2 r; asm("mov.b64 {%0, %1}, %2;" : "=f"(r.x), "=f"(r.y) : "l"(v)); return r;
}
__device__ __forceinline__ void fma2(u64& d, u64 a, u64 b) {
    asm("fma.rn.f32x2 %0, %1, %2, %0;" : "+l"(d) : "l"(a), "l"(b));
}
__device__ __forceinline__ u64 mul2(u64 a, u64 b) {
    u64 r; asm("mul.rn.f32x2 %0, %1, %2;" : "=l"(r) : "l"(a), "l"(b)); return r;
}

__device__ __forceinline__ float gelu_f(float v) {
    return 0.5f * v * (1.0f + erff(v * 0.70710678118654752f));
}

// ---------------------------------------------------------------------------
// SGEMM: C[M,N] = A[M,K] @ B[K,N] + bias (+ GELU | + residual)
// 128x128 block tile, BK=8, 256 threads, 8x8 per thread via f32x2 pairs,
// double-buffered SMEM. blockIdx.z selects among up to 3 (B, bias, C) sets.
// EPI: 0 = bias, 1 = bias+gelu, 2 = bias+residual
// ---------------------------------------------------------------------------
template<int EPI>
__global__ __launch_bounds__(256, 2)
void sgemm_kernel(const float* __restrict__ A,
                  const float* __restrict__ B0, const float* __restrict__ B1,
                  const float* __restrict__ B2,
                  const float* __restrict__ bias0, const float* __restrict__ bias1,
                  const float* __restrict__ bias2,
                  const float* __restrict__ R,
                  float* __restrict__ C0, float* __restrict__ C1, float* __restrict__ C2,
                  int M, int N, int K)
{
    const int z = blockIdx.z;
    const float* B    = (z == 0) ? B0    : (z == 1) ? B1    : B2;
    const float* bias = (z == 0) ? bias0 : (z == 1) ? bias1 : bias2;
    float*       C    = (z == 0) ? C0    : (z == 1) ? C1    : C2;

    __shared__ __align__(16) float As[2][8][132];   // padded: conflict-free transpose
    __shared__ __align__(16) float Bs[2][8][128];

    const int t  = threadIdx.x;
    const int tx = t & 15;
    const int ty = t >> 4;
    const int m0 = blockIdx.y * 128;
    const int n0 = blockIdx.x * 128;

    const int ar = t >> 1;          // 0..127 (A tile row)
    const int ac = (t & 1) * 4;     // 0 or 4 (A tile k-col)
    const int br = t >> 5;          // 0..7   (B tile k-row)
    const int bc = (t & 31) * 4;    // 0..124 (B tile col)

    const float* Ap = A + (size_t)(m0 + ar) * K + ac;
    const float* Bp = B + (size_t)br * N + n0 + bc;

    // prologue: tile 0
    {
        float4 av = *(const float4*)Ap;
        float4 bv = *(const float4*)Bp;
        As[0][ac + 0][ar] = av.x; As[0][ac + 1][ar] = av.y;
        As[0][ac + 2][ar] = av.z; As[0][ac + 3][ar] = av.w;
        *(float4*)&Bs[0][br][bc] = bv;
    }
    __syncthreads();

    u64 acc2[8][4];
    #pragma unroll
    for (int i = 0; i < 8; ++i)
        #pragma unroll
        for (int j = 0; j < 4; ++j) acc2[i][j] = 0ull;

    const int KT = K >> 3;
    int buf = 0;
    for (int kt = 0; kt < KT; ++kt) {
        float4 an, bn;
        const bool more = (kt + 1 < KT);
        if (more) {
            an = *(const float4*)(Ap + (size_t)(kt + 1) * 8);
            bn = *(const float4*)(Bp + (size_t)(kt + 1) * 8 * N);
        }
        #pragma unroll
        for (int k = 0; k < 8; ++k) {
            float4 a0 = *(const float4*)&As[buf][k][ty * 4];
            float4 a1 = *(const float4*)&As[buf][k][ty * 4 + 64];
            float4 b0 = *(const float4*)&Bs[buf][k][tx * 4];
            float4 b1 = *(const float4*)&Bs[buf][k][tx * 4 + 64];
            u64 av[8] = {splat2(a0.x), splat2(a0.y), splat2(a0.z), splat2(a0.w),
                         splat2(a1.x), splat2(a1.y), splat2(a1.z), splat2(a1.w)};
            u64 bv[4] = {pack2(b0.x, b0.y), pack2(b0.z, b0.w),
                         pack2(b1.x, b1.y), pack2(b1.z, b1.w)};
            #pragma unroll
            for (int i = 0; i < 8; ++i)
                #pragma unroll
                for (int j = 0; j < 4; ++j)
                    fma2(acc2[i][j], av[i], bv[j]);
        }
        if (more) {
            const int nb = buf ^ 1;
            As[nb][ac + 0][ar] = an.x; As[nb][ac + 1][ar] = an.y;
            As[nb][ac + 2][ar] = an.z; As[nb][ac + 3][ar] = an.w;
            *(float4*)&Bs[nb][br][bc] = bn;
        }
        __syncthreads();
        buf ^= 1;
    }

    // epilogue
    #pragma unroll
    for (int iq = 0; iq < 2; ++iq)
    #pragma unroll
    for (int i = 0; i < 4; ++i) {
        const int row = m0 + ty * 4 + iq * 64 + i;
        #pragma unroll
        for (int jq = 0; jq < 2; ++jq) {
            const int col = n0 + tx * 4 + jq * 64;
            float4 bb = *(const float4*)&bias[col];
            float2 lo = unpack2(acc2[iq * 4 + i][jq * 2 + 0]);
            float2 hi = unpack2(acc2[iq * 4 + i][jq * 2 + 1]);
            float4 r;
            r.x = lo.x + bb.x; r.y = lo.y + bb.y;
            r.z = hi.x + bb.z; r.w = hi.y + bb.w;
            if (EPI == 1) {
                r.x = gelu_f(r.x); r.y = gelu_f(r.y);
                r.z = gelu_f(r.z); r.w = gelu_f(r.w);
            }
            if (EPI == 2) {
                float4 rv = *(const float4*)&R[(size_t)row * N + col];
                r.x += rv.x; r.y += rv.y; r.z += rv.z; r.w += rv.w;
            }
            *(float4*)&C[(size_t)row * N + col] = r;
        }
    }
}

// ---------------------------------------------------------------------------
// Flash attention, fp32, f32x2 inner loops. One CTA = 64 queries x batch-head.
// ---------------------------------------------------------------------------
__global__ __launch_bounds__(256, 1)
void attn_kernel(const float* __restrict__ Q, const float* __restrict__ K,
                 const float* __restrict__ V, const int* __restrict__ mask,
                 float* __restrict__ Y)
{
    extern __shared__ __align__(16) float sm[];
    float (*Qs)[64] = (float(*)[64])sm;                       // 4096 floats
    float (*KP)[68] = (float(*)[68])(sm + 4096);              // 4352 floats
    float (*Vs)[64] = (float(*)[64])(sm + 4096 + 4352);       // 4096 floats
    int*   mk       = (int*)(sm + 4096 + 4352 + 4096);        // 64 ints

    const int t    = threadIdx.x;
    const int tx   = t & 15;
    const int ty   = t >> 4;
    const int q0   = blockIdx.x * 64;
    const int bh   = blockIdx.y;
    const int tokb = (bh >> 4) * 2048;
    const int colb = (bh & 15) * 64;

    const int lr  = t >> 4;          // 0..15
    const int ld4 = (t & 15) * 4;    // 0..60

    // load Q tile (transposed, pre-scaled by 1/8)
    #pragma unroll
    for (int x = 0; x < 4; ++x) {
        const int i = lr + x * 16;
        float4 v = *(const float4*)&Q[(size_t)(tokb + q0 + i) * 1024 + colb + ld4];
        Qs[ld4 + 0][i] = v.x * 0.125f;
        Qs[ld4 + 1][i] = v.y * 0.125f;
        Qs[ld4 + 2][i] = v.z * 0.125f;
        Qs[ld4 + 3][i] = v.w * 0.125f;
    }

    float m_i[4], l_i[4];
    u64 o2[4][2];
    #pragma unroll
    for (int i = 0; i < 4; ++i) {
        m_i[i] = -1e30f; l_i[i] = 0.0f;
        o2[i][0] = 0ull; o2[i][1] = 0ull;
    }

    for (int kv0 = 0; kv0 < 2048; kv0 += 64) {
        __syncthreads();   // protect KP/Vs reuse across iterations
        #pragma unroll
        for (int x = 0; x < 4; ++x) {
            const int j = lr + x * 16;
            float4 kv = *(const float4*)&K[(size_t)(tokb + kv0 + j) * 1024 + colb + ld4];
            KP[ld4 + 0][j] = kv.x; KP[ld4 + 1][j] = kv.y;
            KP[ld4 + 2][j] = kv.z; KP[ld4 + 3][j] = kv.w;
            float4 vv = *(const float4*)&V[(size_t)(tokb + kv0 + j) * 1024 + colb + ld4];
            *(float4*)&Vs[j][ld4] = vv;
        }
        if (t < 64) mk[t] = mask[tokb + kv0 + t];
        __syncthreads();

        // S tile: 4 rows x 2 f32x2 pairs per thread over d=64
        u64 s2[4][2];
        #pragma unroll
        for (int i = 0; i < 4; ++i) { s2[i][0] = 0ull; s2[i][1] = 0ull; }

        #pragma unroll 8
        for (int d = 0; d < 64; ++d) {
            float4 q4 = *(const float4*)&Qs[d][ty * 4];
            float4 k4 = *(const float4*)&KP[d][tx * 4];
            u64 qs[4] = {splat2(q4.x), splat2(q4.y), splat2(q4.z), splat2(q4.w)};
            u64 ks[2] = {pack2(k4.x, k4.y), pack2(k4.z, k4.w)};
            #pragma unroll
            for (int i = 0; i < 4; ++i) {
                fma2(s2[i][0], qs[i], ks[0]);
                fma2(s2[i][1], qs[i], ks[1]);
            }
        }
        __syncthreads();   // done reading KP as K^T

        // online softmax; write P transposed into KP
        #pragma unroll
        for (int ri = 0; ri < 4; ++ri) {
            float2 sa = unpack2(s2[ri][0]);
            float2 sb = unpack2(s2[ri][1]);
            float s[4] = {sa.x, sa.y, sb.x, sb.y};
            float rm = -1e30f;
            #pragma unroll
            for (int ci = 0; ci < 4; ++ci) {
                if (mk[tx * 4 + ci] == 0) s[ci] = -1e30f;
                rm = fmaxf(rm, s[ci]);
            }
            #pragma unroll
            for (int off = 1; off < 16; off <<= 1)
                rm = fmaxf(rm, __shfl_xor_sync(0xffffffffu, rm, off));
            const float mn    = fmaxf(m_i[ri], rm);
            const float alpha = __expf(m_i[ri] - mn);
            float rs = 0.0f;
            float p[4];
            #pragma unroll
            for (int ci = 0; ci < 4; ++ci) {
                p[ci] = __expf(s[ci] - mn);
                rs += p[ci];
            }
            #pragma unroll
            for (int off = 1; off < 16; off <<= 1)
                rs += __shfl_xor_sync(0xffffffffu, rs, off);
            l_i[ri] = l_i[ri] * alpha + rs;
            m_i[ri] = mn;
            const u64 al2 = splat2(alpha);
            o2[ri][0] = mul2(o2[ri][0], al2);
            o2[ri][1] = mul2(o2[ri][1], al2);
            #pragma unroll
            for (int ci = 0; ci < 4; ++ci)
                KP[tx * 4 + ci][ty * 4 + ri] = p[ci];   // P^T
        }
        __syncthreads();

        // O += P @ V
        #pragma unroll 8
        for (int j = 0; j < 64; ++j) {
            float4 p4 = *(const float4*)&KP[j][ty * 4];
            float4 v4 = *(const float4*)&Vs[j][tx * 4];
            u64 ps[4] = {splat2(p4.x), splat2(p4.y), splat2(p4.z), splat2(p4.w)};
            u64 vs[2] = {pack2(v4.x, v4.y), pack2(v4.z, v4.w)};
            #pragma unroll
            for (int i = 0; i < 4; ++i) {
                fma2(o2[i][0], ps[i], vs[0]);
                fma2(o2[i][1], ps[i], vs[1]);
            }
        }
    }

    #pragma unroll
    for (int ri = 0; ri < 4; ++ri) {
        const float inv = 1.0f / l_i[ri];
        float2 lo = unpack2(o2[ri][0]);
        float2 hi = unpack2(o2[ri][1]);
        float4 r;
        r.x = lo.x * inv; r.y = lo.y * inv;
        r.z = hi.x * inv; r.w = hi.y * inv;
        *(float4*)&Y[(size_t)(tokb + q0 + ty * 4 + ri) * 1024 + colb + tx * 4] = r;
    }
}

// ---------------------------------------------------------------------------
// LayerNorm: one row (1024) per CTA, 256 threads, biased variance, eps=1e-5
// ---------------------------------------------------------------------------
__global__ __launch_bounds__(256)
void ln_kernel(const float* __restrict__ X, const float* __restrict__ w,
               const float* __restrict__ b, float* __restrict__ out)
{
    __shared__ float red[2][8];
    const int t = threadIdx.x;
    const size_t row = blockIdx.x;
    float4 xv = *(const float4*)&X[row * 1024 + t * 4];
    float s  = xv.x + xv.y + xv.z + xv.w;
    float s2 = xv.x * xv.x + xv.y * xv.y + xv.z * xv.z + xv.w * xv.w;
    #pragma unroll
    for (int off = 16; off; off >>= 1) {
        s  += __shfl_xor_sync(0xffffffffu, s,  off);
        s2 += __shfl_xor_sync(0xffffffffu, s2, off);
    }
    if ((t & 31) == 0) { red[0][t >> 5] = s; red[1][t >> 5] = s2; }
    __syncthreads();
    float S = 0.0f, S2 = 0.0f;
    #pragma unroll
    for (int i = 0; i < 8; ++i) { S += red[0][i]; S2 += red[1][i]; }
    const float mean = S * (1.0f / 1024.0f);
    const float var  = S2 * (1.0f / 1024.0f) - mean * mean;
    const float rstd = rsqrtf(var + 1e-5f);
    float4 wv = *(const float4*)&w[t * 4];
    float4 bv = *(const float4*)&b[t * 4];
    float4 r;
    r.x = (xv.x - mean) * rstd * wv.x + bv.x;
    r.y = (xv.y - mean) * rstd * wv.y + bv.y;
    r.z = (xv.z - mean) * rstd * wv.z + bv.z;
    r.w = (xv.w - mean) * rstd * wv.w + bv.w;
    *(float4*)&out[row * 1024 + t * 4] = r;
}

// ---------------------------------------------------------------------------
// launch
// ---------------------------------------------------------------------------
extern "C" void kernel_launch(void* const* d_in, const int* in_sizes, int n_in,
                              void* d_out, int out_size)
{
    (void)in_sizes; (void)n_in; (void)out_size;
    const float* x    = (const float*)d_in[0];
    const int*   mask = (const int*)  d_in[1];
    const float* WQ   = (const float*)d_in[2];
    const float* bQ   = (const float*)d_in[3];
    const float* WK   = (const float*)d_in[4];
    const float* bK   = (const float*)d_in[5];
    const float* WV   = (const float*)d_in[6];
    const float* bV   = (const float*)d_in[7];
    const float* WY   = (const float*)d_in[8];
    const float* bY   = (const float*)d_in[9];
    const float* ln1w = (const float*)d_in[10];
    const float* ln1b = (const float*)d_in[11];
    const float* ln2w = (const float*)d_in[12];
    const float* ln2b = (const float*)d_in[13];
    const float* W1   = (const float*)d_in[14];
    const float* b1   = (const float*)d_in[15];
    const float* W2   = (const float*)d_in[16];
    const float* b2   = (const float*)d_in[17];
    float* out = (float*)d_out;

    float *Qp, *Kp, *Vp, *Yp, *FFp;
    cudaGetSymbolAddress((void**)&Qp,  g_Q);
    cudaGetSymbolAddress((void**)&Kp,  g_K);
    cudaGetSymbolAddress((void**)&Vp,  g_V);
    cudaGetSymbolAddress((void**)&Yp,  g_Y);
    cudaGetSymbolAddress((void**)&FFp, g_FF);

    const int ATTN_SMEM = (4096 + 4352 + 4096 + 64) * 4;  // 50432 bytes
    cudaFuncSetAttribute(attn_kernel,
                         cudaFuncAttributeMaxDynamicSharedMemorySize, ATTN_SMEM);

    dim3 blk(256);

    // QKV projections fused into one launch (grid.z selects W/b/C)
    sgemm_kernel<0><<<dim3(8, 32, 3), blk>>>(x, WQ, WK, WV, bQ, bK, bV,
                                             nullptr, Qp, Kp, Vp, 4096, 1024, 1024);

    // attention -> g_Y
    attn_kernel<<<dim3(32, 32), blk, ATTN_SMEM>>>(Qp, Kp, Vp, mask, Yp);

    // a + x = y@WY + bY + x   -> g_Q
    sgemm_kernel<2><<<dim3(8, 32, 1), blk>>>(Yp, WY, WY, WY, bY, bY, bY,
                                             x, Qp, Qp, Qp, 4096, 1024, 1024);

    // h = LN1(a + x)          -> g_K
    ln_kernel<<<4096, blk>>>(Qp, ln1w, ln1b, Kp);

    // gelu(h@W1 + b1)         -> g_FF
    sgemm_kernel<1><<<dim3(32, 32, 1), blk>>>(Kp, W1, W1, W1, b1, b1, b1,
                                              nullptr, FFp, FFp, FFp, 4096, 4096, 1024);

    // ff@W2 + b2 + h          -> g_V
    sgemm_kernel<2><<<dim3(8, 32, 1), blk>>>(FFp, W2, W2, W2, b2, b2, b2,
                                             Kp, Vp, Vp, Vp, 4096, 1024, 4096);

    // out = LN2(ff + h)       -> d_out
    ln_kernel<<<4096, blk>>>(Vp, ln2w, ln2b, out);
}

// round 4
// speedup vs baseline: 1.4384x; 1.4384x over previous
#include <cuda_runtime.h>
#include <cuda_bf16.h>
#include <math.h>
#include <stdint.h>

// ---------------------------------------------------------------------------
// Scratch (__device__ globals; no allocations allowed)
// ---------------------------------------------------------------------------
__device__ float g_Q [(size_t)4096 * 1024];
__device__ float g_K [(size_t)4096 * 1024];
__device__ float g_V [(size_t)4096 * 1024];
__device__ float g_Y [(size_t)4096 * 1024];
__device__ float g_FF[(size_t)4096 * 4096];
// bf16 split buffers (stored as u16)
__device__ unsigned short g_Ahi[(size_t)4096 * 4096];
__device__ unsigned short g_Alo[(size_t)4096 * 4096];
__device__ unsigned short g_Whi[(size_t)12 * 1024 * 1024];
__device__ unsigned short g_Wlo[(size_t)12 * 1024 * 1024];

__device__ __forceinline__ uint32_t smem_u32(const void* p) {
    uint32_t a;
    asm("{ .reg .u64 t; cvta.to.shared.u64 t, %1; cvt.u32.u64 %0, t; }"
        : "=r"(a) : "l"(p));
    return a;
}

__device__ __forceinline__ void cpa16(uint32_t s, const void* g) {
    asm volatile("cp.async.cg.shared.global [%0], [%1], 16;"
                 :: "r"(s), "l"(__cvta_generic_to_global(g)) : "memory");
}
__device__ __forceinline__ void cp_commit() {
    asm volatile("cp.async.commit_group;" ::: "memory");
}
template<int N>
__device__ __forceinline__ void cp_wait() {
    asm volatile("cp.async.wait_group %0;" :: "n"(N) : "memory");
}

__device__ __forceinline__ void ldm_x4(uint32_t* r, uint32_t saddr) {
    asm volatile("ldmatrix.sync.aligned.m8n8.x4.shared.b16 {%0,%1,%2,%3}, [%4];"
                 : "=r"(r[0]), "=r"(r[1]), "=r"(r[2]), "=r"(r[3]) : "r"(saddr));
}

__device__ __forceinline__ void mma16816(float* c, const uint32_t* a, const uint32_t* b) {
    asm volatile("mma.sync.aligned.m16n8k16.row.col.f32.bf16.bf16.f32 "
                 "{%0,%1,%2,%3}, {%4,%5,%6,%7}, {%8,%9}, {%0,%1,%2,%3};"
                 : "+f"(c[0]), "+f"(c[1]), "+f"(c[2]), "+f"(c[3])
                 : "r"(a[0]), "r"(a[1]), "r"(a[2]), "r"(a[3]),
                   "r"(b[0]), "r"(b[1]));
}

__device__ __forceinline__ float gelu_f(float v) {
    return 0.5f * v * (1.0f + erff(v * 0.70710678118654752f));
}

// ---------------------------------------------------------------------------
// Tensor-core GEMM via mma.sync (bf16 3-product split, fp32 accumulate)
// C[M,N] = (Ahi+Alo)[M,K] @ (Whi+Wlo)[N,K]^T  (+bias | +bias,gelu | +bias+res)
// CTA tile 128x128, 8 warps (2x4), warp tile 64x32, k-chunk 32, 3-stage cp.async.
// SMEM stage: 4 tiles (Ahi,Alo,Bhi,Blo), each 128 rows x 64B data, 80B stride.
// ---------------------------------------------------------------------------
#define ROWB   80
#define TILEB  (128 * ROWB)          // 10240
#define STAGEB (4 * TILEB)           // 40960
#define NSTAGE 3
#define TG_SMEM (NSTAGE * STAGEB)    // 122880

template<int EPI>
__global__ __launch_bounds__(256, 1)
void tgemm_kernel(const unsigned short* __restrict__ Ahi16,
                  const unsigned short* __restrict__ Alo16,
                  const unsigned short* __restrict__ Whi16,
                  const unsigned short* __restrict__ Wlo16,
                  size_t wz,
                  const float* __restrict__ bias0, const float* __restrict__ bias1,
                  const float* __restrict__ bias2,
                  const float* __restrict__ R,
                  float* __restrict__ C0, float* __restrict__ C1, float* __restrict__ C2,
                  int M, int N, int K)
{
    extern __shared__ __align__(128) char smem[];
    const int z = blockIdx.z;
    const unsigned short* Bh = Whi16 + wz * z;
    const unsigned short* Bl = Wlo16 + wz * z;
    const float* bias = (z == 0) ? bias0 : (z == 1) ? bias1 : bias2;
    float*       C    = (z == 0) ? C0    : (z == 1) ? C1    : C2;

    const uint32_t sbase = smem_u32(smem);
    const int t    = threadIdx.x;
    const int wid  = t >> 5;
    const int lane = t & 31;
    const int m0   = blockIdx.y * 128;
    const int n0   = blockIdx.x * 128;
    const int wm   = (wid & 1) * 64;       // warp M offset in tile
    const int wn   = (wid >> 1) * 32;      // warp N offset in tile

    // ---- loader mapping: 8 cp.async of 16B per thread per stage ----
    const int lrow = t >> 1;               // 0..127
    const int lu   = (t & 1) * 2;          // 16B unit 0/2
    const unsigned short* pAh = Ahi16 + (size_t)(m0 + lrow) * K + lu * 8;
    const unsigned short* pAl = Alo16 + (size_t)(m0 + lrow) * K + lu * 8;
    const unsigned short* pBh = Bh    + (size_t)(n0 + lrow) * K + lu * 8;
    const unsigned short* pBl = Bl    + (size_t)(n0 + lrow) * K + lu * 8;
    const uint32_t sRow = (uint32_t)lrow * ROWB + lu * 16;

    #define LOAD_STAGE(cc, ss) do {                                        \
        const uint32_t sb_ = sbase + (ss) * STAGEB + sRow;                  \
        const size_t  ko_ = (size_t)(cc) * 32;                              \
        cpa16(sb_ + 0 * TILEB,      pAh + ko_);                             \
        cpa16(sb_ + 0 * TILEB + 16, pAh + ko_ + 8);                         \
        cpa16(sb_ + 1 * TILEB,      pAl + ko_);                             \
        cpa16(sb_ + 1 * TILEB + 16, pAl + ko_ + 8);                         \
        cpa16(sb_ + 2 * TILEB,      pBh + ko_);                             \
        cpa16(sb_ + 2 * TILEB + 16, pBh + ko_ + 8);                         \
        cpa16(sb_ + 3 * TILEB,      pBl + ko_);                             \
        cpa16(sb_ + 3 * TILEB + 16, pBl + ko_ + 8);                         \
    } while (0)

    // ---- ldmatrix per-lane byte offsets ----
    const uint32_t laneA = (uint32_t)(lane & 15) * ROWB + (lane >> 4) * 16;
    const uint32_t laneB = (uint32_t)((lane & 7) + ((lane >> 4) << 3)) * ROWB
                         + ((lane >> 3) & 1) * 16;

    float acc[4][4][4];
    #pragma unroll
    for (int i = 0; i < 4; ++i)
        #pragma unroll
        for (int j = 0; j < 4; ++j)
            #pragma unroll
            for (int q = 0; q < 4; ++q) acc[i][j][q] = 0.0f;

    const int NC = K >> 5;   // k-chunks of 32

    // prologue: fill pipeline
    LOAD_STAGE(0, 0); cp_commit();
    LOAD_STAGE(1, 1); cp_commit();
    LOAD_STAGE(2, 2); cp_commit();

    for (int c = 0; c < NC; ++c) {
        const int s = c % NSTAGE;
        cp_wait<NSTAGE - 1>();
        __syncthreads();

        const uint32_t stg = sbase + s * STAGEB;
        #pragma unroll
        for (int ks = 0; ks < 2; ++ks) {
            const uint32_t kb = ks * 32;
            uint32_t ah[4][4], al[4][4], bh[4][2], bl[4][2];
            #pragma unroll
            for (int mf = 0; mf < 4; ++mf) {
                const uint32_t ra = stg + (uint32_t)(wm + mf * 16) * ROWB + laneA + kb;
                ldm_x4(ah[mf], ra + 0 * TILEB);
                ldm_x4(al[mf], ra + 1 * TILEB);
            }
            #pragma unroll
            for (int p = 0; p < 2; ++p) {
                uint32_t rb[4], rl[4];
                const uint32_t ra = stg + (uint32_t)(wn + p * 16) * ROWB + laneB + kb;
                ldm_x4(rb, ra + 2 * TILEB);
                ldm_x4(rl, ra + 3 * TILEB);
                bh[p * 2 + 0][0] = rb[0]; bh[p * 2 + 0][1] = rb[1];
                bh[p * 2 + 1][0] = rb[2]; bh[p * 2 + 1][1] = rb[3];
                bl[p * 2 + 0][0] = rl[0]; bl[p * 2 + 0][1] = rl[1];
                bl[p * 2 + 1][0] = rl[2]; bl[p * 2 + 1][1] = rl[3];
            }
            #pragma unroll
            for (int mf = 0; mf < 4; ++mf)
                #pragma unroll
                for (int nf = 0; nf < 4; ++nf) {
                    mma16816(acc[mf][nf], ah[mf], bh[nf]);
                    mma16816(acc[mf][nf], ah[mf], bl[nf]);
                    mma16816(acc[mf][nf], al[mf], bh[nf]);
                }
        }
        __syncthreads();
        if (c + NSTAGE < NC) LOAD_STAGE(c + NSTAGE, s);
        cp_commit();   // keep group count consistent (empty groups are fine)
    }

    // ---- epilogue: registers -> GMEM, fused bias/gelu/residual ----
    const int rbase = lane >> 2;            // 0..7
    const int cbase = (lane & 3) * 2;       // 0,2,4,6
    #pragma unroll
    for (int mf = 0; mf < 4; ++mf) {
        #pragma unroll
        for (int nf = 0; nf < 4; ++nf) {
            const int col = n0 + wn + nf * 8 + cbase;
            const float2 bb = *(const float2*)&bias[col];
            #pragma unroll
            for (int h = 0; h < 2; ++h) {
                const int row = m0 + wm + mf * 16 + rbase + h * 8;
                float2 rv;
                rv.x = acc[mf][nf][h * 2 + 0] + bb.x;
                rv.y = acc[mf][nf][h * 2 + 1] + bb.y;
                if (EPI == 1) { rv.x = gelu_f(rv.x); rv.y = gelu_f(rv.y); }
                if (EPI == 2) {
                    const float2 rr = *(const float2*)&R[(size_t)row * N + col];
                    rv.x += rr.x; rv.y += rr.y;
                }
                *(float2*)&C[(size_t)row * N + col] = rv;
            }
        }
    }
    #undef LOAD_STAGE
}

// ---------------------------------------------------------------------------
// Elementwise fp32 -> bf16 hi/lo split (row-major preserved)
// ---------------------------------------------------------------------------
__device__ __forceinline__ void split1(float v, unsigned short& h, unsigned short& l) {
    __nv_bfloat16 hb = __float2bfloat16(v);
    __nv_bfloat16 lb = __float2bfloat16(v - __bfloat162float(hb));
    h = *(unsigned short*)&hb;
    l = *(unsigned short*)&lb;
}

__global__ __launch_bounds__(256)
void split_kernel(const float* __restrict__ X, unsigned short* __restrict__ hi,
                  unsigned short* __restrict__ lo, int n4)
{
    int i = blockIdx.x * 256 + threadIdx.x;
    if (i >= n4) return;
    float4 v = ((const float4*)X)[i];
    ushort4 h, l;
    split1(v.x, h.x, l.x); split1(v.y, h.y, l.y);
    split1(v.z, h.z, l.z); split1(v.w, h.w, l.w);
    ((ushort4*)hi)[i] = h;
    ((ushort4*)lo)[i] = l;
}

// ---------------------------------------------------------------------------
// Weight transpose + split: W[K,N] fp32 -> Thi/Tlo[N,K] bf16
// ---------------------------------------------------------------------------
__global__ __launch_bounds__(256)
void tsplit_kernel(const float* __restrict__ W, unsigned short* __restrict__ Thi,
                   unsigned short* __restrict__ Tlo, int K, int N)
{
    __shared__ float s[32][33];
    const int tx = threadIdx.x, ty = threadIdx.y;
    const int nb = blockIdx.x * 32, kb = blockIdx.y * 32;
    #pragma unroll
    for (int i = 0; i < 4; ++i)
        s[ty + i * 8][tx] = W[(size_t)(kb + ty + i * 8) * N + nb + tx];
    __syncthreads();
    #pragma unroll
    for (int i = 0; i < 4; ++i) {
        const float v = s[tx][ty + i * 8];
        unsigned short h, l;
        split1(v, h, l);
        const size_t o = (size_t)(nb + ty + i * 8) * K + kb + tx;
        Thi[o] = h; Tlo[o] = l;
    }
}

// ---------------------------------------------------------------------------
// Flash attention, fp32 scalar (R1 version). One CTA = 64 queries x batch-head.
// ---------------------------------------------------------------------------
__global__ __launch_bounds__(256, 1)
void attn_kernel(const float* __restrict__ Q, const float* __restrict__ K,
                 const float* __restrict__ V, const int* __restrict__ mask,
                 float* __restrict__ Y)
{
    extern __shared__ __align__(16) float sm[];
    float (*Qs)[64] = (float(*)[64])sm;
    float (*KP)[68] = (float(*)[68])(sm + 4096);
    float (*Vs)[64] = (float(*)[64])(sm + 4096 + 4352);
    int*   mk       = (int*)(sm + 4096 + 4352 + 4096);

    const int t    = threadIdx.x;
    const int tx   = t & 15;
    const int ty   = t >> 4;
    const int q0   = blockIdx.x * 64;
    const int bh   = blockIdx.y;
    const int tokb = (bh >> 4) * 2048;
    const int colb = (bh & 15) * 64;

    const int lr  = t >> 4;
    const int ld4 = (t & 15) * 4;

    #pragma unroll
    for (int x = 0; x < 4; ++x) {
        const int i = lr + x * 16;
        float4 v = *(const float4*)&Q[(size_t)(tokb + q0 + i) * 1024 + colb + ld4];
        Qs[ld4 + 0][i] = v.x * 0.125f;
        Qs[ld4 + 1][i] = v.y * 0.125f;
        Qs[ld4 + 2][i] = v.z * 0.125f;
        Qs[ld4 + 3][i] = v.w * 0.125f;
    }

    float m_i[4], l_i[4], o[4][4];
    #pragma unroll
    for (int i = 0; i < 4; ++i) {
        m_i[i] = -1e30f; l_i[i] = 0.0f;
        #pragma unroll
        for (int j = 0; j < 4; ++j) o[i][j] = 0.0f;
    }

    for (int kv0 = 0; kv0 < 2048; kv0 += 64) {
        __syncthreads();
        #pragma unroll
        for (int x = 0; x < 4; ++x) {
            const int j = lr + x * 16;
            float4 kv = *(const float4*)&K[(size_t)(tokb + kv0 + j) * 1024 + colb + ld4];
            KP[ld4 + 0][j] = kv.x; KP[ld4 + 1][j] = kv.y;
            KP[ld4 + 2][j] = kv.z; KP[ld4 + 3][j] = kv.w;
            float4 vv = *(const float4*)&V[(size_t)(tokb + kv0 + j) * 1024 + colb + ld4];
            *(float4*)&Vs[j][ld4] = vv;
        }
        if (t < 64) mk[t] = mask[tokb + kv0 + t];
        __syncthreads();

        float s[4][4];
        #pragma unroll
        for (int i = 0; i < 4; ++i)
            #pragma unroll
            for (int j = 0; j < 4; ++j) s[i][j] = 0.0f;

        #pragma unroll 8
        for (int d = 0; d < 64; ++d) {
            float4 q4 = *(const float4*)&Qs[d][ty * 4];
            float4 k4 = *(const float4*)&KP[d][tx * 4];
            float qa[4] = {q4.x, q4.y, q4.z, q4.w};
            float kb[4] = {k4.x, k4.y, k4.z, k4.w};
            #pragma unroll
            for (int i = 0; i < 4; ++i)
                #pragma unroll
                for (int j = 0; j < 4; ++j)
                    s[i][j] = fmaf(qa[i], kb[j], s[i][j]);
        }
        __syncthreads();

        #pragma unroll
        for (int ri = 0; ri < 4; ++ri) {
            float rm = -1e30f;
            #pragma unroll
            for (int ci = 0; ci < 4; ++ci) {
                if (mk[tx * 4 + ci] == 0) s[ri][ci] = -1e30f;
                rm = fmaxf(rm, s[ri][ci]);
            }
            #pragma unroll
            for (int off = 1; off < 16; off <<= 1)
                rm = fmaxf(rm, __shfl_xor_sync(0xffffffffu, rm, off));
            const float mn    = fmaxf(m_i[ri], rm);
            const float alpha = __expf(m_i[ri] - mn);
            float rs = 0.0f;
            float p[4];
            #pragma unroll
            for (int ci = 0; ci < 4; ++ci) {
                p[ci] = __expf(s[ri][ci] - mn);
                rs += p[ci];
            }
            #pragma unroll
            for (int off = 1; off < 16; off <<= 1)
                rs += __shfl_xor_sync(0xffffffffu, rs, off);
            l_i[ri] = l_i[ri] * alpha + rs;
            m_i[ri] = mn;
            #pragma unroll
            for (int ci = 0; ci < 4; ++ci) {
                o[ri][ci] *= alpha;
                KP[tx * 4 + ci][ty * 4 + ri] = p[ci];
            }
        }
        __syncthreads();

        #pragma unroll 8
        for (int j = 0; j < 64; ++j) {
            float4 p4 = *(const float4*)&KP[j][ty * 4];
            float4 v4 = *(const float4*)&Vs[j][tx * 4];
            float pa[4] = {p4.x, p4.y, p4.z, p4.w};
            float vb[4] = {v4.x, v4.y, v4.z, v4.w};
            #pragma unroll
            for (int i = 0; i < 4; ++i)
                #pragma unroll
                for (int c = 0; c < 4; ++c)
                    o[i][c] = fmaf(pa[i], vb[c], o[i][c]);
        }
    }

    #pragma unroll
    for (int ri = 0; ri < 4; ++ri) {
        const float inv = 1.0f / l_i[ri];
        float4 r;
        r.x = o[ri][0] * inv; r.y = o[ri][1] * inv;
        r.z = o[ri][2] * inv; r.w = o[ri][3] * inv;
        *(float4*)&Y[(size_t)(tokb + q0 + ty * 4 + ri) * 1024 + colb + tx * 4] = r;
    }
}

// ---------------------------------------------------------------------------
// LayerNorm: one row (1024) per CTA
// ---------------------------------------------------------------------------
__global__ __launch_bounds__(256)
void ln_kernel(const float* __restrict__ X, const float* __restrict__ w,
               const float* __restrict__ b, float* __restrict__ out)
{
    __shared__ float red[2][8];
    const int t = threadIdx.x;
    const size_t row = blockIdx.x;
    float4 xv = *(const float4*)&X[row * 1024 + t * 4];
    float s  = xv.x + xv.y + xv.z + xv.w;
    float s2 = xv.x * xv.x + xv.y * xv.y + xv.z * xv.z + xv.w * xv.w;
    #pragma unroll
    for (int off = 16; off; off >>= 1) {
        s  += __shfl_xor_sync(0xffffffffu, s,  off);
        s2 += __shfl_xor_sync(0xffffffffu, s2, off);
    }
    if ((t & 31) == 0) { red[0][t >> 5] = s; red[1][t >> 5] = s2; }
    __syncthreads();
    float S = 0.0f, S2 = 0.0f;
    #pragma unroll
    for (int i = 0; i < 8; ++i) { S += red[0][i]; S2 += red[1][i]; }
    const float mean = S * (1.0f / 1024.0f);
    const float var  = S2 * (1.0f / 1024.0f) - mean * mean;
    const float rstd = rsqrtf(var + 1e-5f);
    float4 wv = *(const float4*)&w[t * 4];
    float4 bv = *(const float4*)&b[t * 4];
    float4 r;
    r.x = (xv.x - mean) * rstd * wv.x + bv.x;
    r.y = (xv.y - mean) * rstd * wv.y + bv.y;
    r.z = (xv.z - mean) * rstd * wv.z + bv.z;
    r.w = (xv.w - mean) * rstd * wv.w + bv.w;
    *(float4*)&out[row * 1024 + t * 4] = r;
}

// ---------------------------------------------------------------------------
// launch
// ---------------------------------------------------------------------------
extern "C" void kernel_launch(void* const* d_in, const int* in_sizes, int n_in,
                              void* d_out, int out_size)
{
    (void)in_sizes; (void)n_in; (void)out_size;
    const float* x    = (const float*)d_in[0];
    const int*   mask = (const int*)  d_in[1];
    const float* WQ   = (const float*)d_in[2];
    const float* bQ   = (const float*)d_in[3];
    const float* WK   = (const float*)d_in[4];
    const float* bK   = (const float*)d_in[5];
    const float* WV   = (const float*)d_in[6];
    const float* bV   = (const float*)d_in[7];
    const float* WY   = (const float*)d_in[8];
    const float* bY   = (const float*)d_in[9];
    const float* ln1w = (const float*)d_in[10];
    const float* ln1b = (const float*)d_in[11];
    const float* ln2w = (const float*)d_in[12];
    const float* ln2b = (const float*)d_in[13];
    const float* W1   = (const float*)d_in[14];
    const float* b1   = (const float*)d_in[15];
    const float* W2   = (const float*)d_in[16];
    const float* b2   = (const float*)d_in[17];
    float* out = (float*)d_out;

    float *Qp, *Kp, *Vp, *Yp, *FFp;
    unsigned short *Ahi, *Alo, *Whi, *Wlo;
    cudaGetSymbolAddress((void**)&Qp,  g_Q);
    cudaGetSymbolAddress((void**)&Kp,  g_K);
    cudaGetSymbolAddress((void**)&Vp,  g_V);
    cudaGetSymbolAddress((void**)&Yp,  g_Y);
    cudaGetSymbolAddress((void**)&FFp, g_FF);
    cudaGetSymbolAddress((void**)&Ahi, g_Ahi);
    cudaGetSymbolAddress((void**)&Alo, g_Alo);
    cudaGetSymbolAddress((void**)&Whi, g_Whi);
    cudaGetSymbolAddress((void**)&Wlo, g_Wlo);

    const size_t MB = (size_t)1024 * 1024;

    const int ATTN_SMEM = (4096 + 4352 + 4096 + 64) * 4;
    cudaFuncSetAttribute(attn_kernel,
                         cudaFuncAttributeMaxDynamicSharedMemorySize, ATTN_SMEM);
    cudaFuncSetAttribute(tgemm_kernel<0>,
                         cudaFuncAttributeMaxDynamicSharedMemorySize, TG_SMEM);
    cudaFuncSetAttribute(tgemm_kernel<1>,
                         cudaFuncAttributeMaxDynamicSharedMemorySize, TG_SMEM);
    cudaFuncSetAttribute(tgemm_kernel<2>,
                         cudaFuncAttributeMaxDynamicSharedMemorySize, TG_SMEM);

    dim3 blk(256);
    dim3 tsb(32, 8);

    // weight transpose + split
    tsplit_kernel<<<dim3(32, 32),  tsb>>>(WQ, Whi + 0 * MB, Wlo + 0 * MB, 1024, 1024);
    tsplit_kernel<<<dim3(32, 32),  tsb>>>(WK, Whi + 1 * MB, Wlo + 1 * MB, 1024, 1024);
    tsplit_kernel<<<dim3(32, 32),  tsb>>>(WV, Whi + 2 * MB, Wlo + 2 * MB, 1024, 1024);
    tsplit_kernel<<<dim3(32, 32),  tsb>>>(WY, Whi + 3 * MB, Wlo + 3 * MB, 1024, 1024);
    tsplit_kernel<<<dim3(128, 32), tsb>>>(W1, Whi + 4 * MB, Wlo + 4 * MB, 1024, 4096);
    tsplit_kernel<<<dim3(32, 128), tsb>>>(W2, Whi + 8 * MB, Wlo + 8 * MB, 4096, 1024);

    // x split
    split_kernel<<<4096, blk>>>(x, Ahi, Alo, (4096 * 1024) / 4);

    // QKV (fused z)
    tgemm_kernel<0><<<dim3(8, 32, 3), blk, TG_SMEM>>>(
        Ahi, Alo, Whi, Wlo, MB, bQ, bK, bV, nullptr, Qp, Kp, Vp, 4096, 1024, 1024);

    // attention
    attn_kernel<<<dim3(32, 32), blk, ATTN_SMEM>>>(Qp, Kp, Vp, mask, Yp);

    // out-proj + residual x -> g_Q
    split_kernel<<<4096, blk>>>(Yp, Ahi, Alo, (4096 * 1024) / 4);
    tgemm_kernel<2><<<dim3(8, 32, 1), blk, TG_SMEM>>>(
        Ahi, Alo, Whi + 3 * MB, Wlo + 3 * MB, 0, bY, bY, bY, x, Qp, Qp, Qp,
        4096, 1024, 1024);

    // h = LN1 -> g_K
    ln_kernel<<<4096, blk>>>(Qp, ln1w, ln1b, Kp);

    // FFN1: gelu(h@W1+b1) -> g_FF
    split_kernel<<<4096, blk>>>(Kp, Ahi, Alo, (4096 * 1024) / 4);
    tgemm_kernel<1><<<dim3(32, 32, 1), blk, TG_SMEM>>>(
        Ahi, Alo, Whi + 4 * MB, Wlo + 4 * MB, 0, b1, b1, b1, nullptr, FFp, FFp, FFp,
        4096, 4096, 1024);

    // FFN2: ff@W2+b2+h -> g_V
    split_kernel<<<16384, blk>>>(FFp, Ahi, Alo, (4096 * 4096) / 4);
    tgemm_kernel<2><<<dim3(8, 32, 1), blk, TG_SMEM>>>(
        Ahi, Alo, Whi + 8 * MB, Wlo + 8 * MB, 0, b2, b2, b2, Kp, Vp, Vp, Vp,
        4096, 1024, 4096);

    // out = LN2
    ln_kernel<<<4096, blk>>>(Vp, ln2w, ln2b, out);
}

// round 5
// speedup vs baseline: 2.0666x; 1.4367x over previous
#include <cuda_runtime.h>
#include <cuda_bf16.h>
#include <math.h>
#include <stdint.h>

// ---------------------------------------------------------------------------
// Scratch (__device__ globals; no allocations allowed)
// ---------------------------------------------------------------------------
__device__ float g_Q [(size_t)4096 * 1024];
__device__ float g_K [(size_t)4096 * 1024];
__device__ float g_V [(size_t)4096 * 1024];
__device__ float g_Y [(size_t)4096 * 1024];
__device__ float g_FF[(size_t)4096 * 4096];
__device__ unsigned short g_Ahi[(size_t)4096 * 4096];
__device__ unsigned short g_Alo[(size_t)4096 * 4096];
__device__ unsigned short g_Whi[(size_t)12 * 1024 * 1024];
__device__ unsigned short g_Wlo[(size_t)12 * 1024 * 1024];
// attention bf16 operands
__device__ unsigned short g_Qhi [(size_t)4096 * 1024];
__device__ unsigned short g_Qlo [(size_t)4096 * 1024];
__device__ unsigned short g_Khi [(size_t)4096 * 1024];
__device__ unsigned short g_Klo [(size_t)4096 * 1024];
__device__ unsigned short g_Vthi[(size_t)1024 * 4096];
__device__ unsigned short g_Vtlo[(size_t)1024 * 4096];

__device__ __forceinline__ uint32_t smem_u32(const void* p) {
    uint32_t a;
    asm("{ .reg .u64 t; cvta.to.shared.u64 t, %1; cvt.u32.u64 %0, t; }"
        : "=r"(a) : "l"(p));
    return a;
}
__device__ __forceinline__ void cpa16(uint32_t s, const void* g) {
    asm volatile("cp.async.cg.shared.global [%0], [%1], 16;"
                 :: "r"(s), "l"(__cvta_generic_to_global(g)) : "memory");
}
__device__ __forceinline__ void cp_commit() {
    asm volatile("cp.async.commit_group;" ::: "memory");
}
template<int N>
__device__ __forceinline__ void cp_wait() {
    asm volatile("cp.async.wait_group %0;" :: "n"(N) : "memory");
}
__device__ __forceinline__ void ldm_x4(uint32_t* r, uint32_t saddr) {
    asm volatile("ldmatrix.sync.aligned.m8n8.x4.shared.b16 {%0,%1,%2,%3}, [%4];"
                 : "=r"(r[0]), "=r"(r[1]), "=r"(r[2]), "=r"(r[3]) : "r"(saddr));
}
__device__ __forceinline__ void mma16816(float* c, const uint32_t* a, const uint32_t* b) {
    asm volatile("mma.sync.aligned.m16n8k16.row.col.f32.bf16.bf16.f32 "
                 "{%0,%1,%2,%3}, {%4,%5,%6,%7}, {%8,%9}, {%0,%1,%2,%3};"
                 : "+f"(c[0]), "+f"(c[1]), "+f"(c[2]), "+f"(c[3])
                 : "r"(a[0]), "r"(a[1]), "r"(a[2]), "r"(a[3]),
                   "r"(b[0]), "r"(b[1]));
}
__device__ __forceinline__ float gelu_f(float v) {
    return 0.5f * v * (1.0f + erff(v * 0.70710678118654752f));
}
// split pair (x = element k, y = element k+1) into packed bf16x2 hi & lo parts
__device__ __forceinline__ void bfsplit2(float x, float y, uint32_t& hi, uint32_t& lo) {
    __nv_bfloat16 hx = __float2bfloat16(x), hy = __float2bfloat16(y);
    hi = ((uint32_t)(*(unsigned short*)&hy) << 16) | (uint32_t)(*(unsigned short*)&hx);
    __nv_bfloat16 lx = __float2bfloat16(x - __bfloat162float(hx));
    __nv_bfloat16 ly = __float2bfloat16(y - __bfloat162float(hy));
    lo = ((uint32_t)(*(unsigned short*)&ly) << 16) | (uint32_t)(*(unsigned short*)&lx);
}

// ---------------------------------------------------------------------------
// Tensor-core dense GEMM (unchanged from R4)
// ---------------------------------------------------------------------------
#define ROWB   80
#define TILEB  (128 * ROWB)
#define STAGEB (4 * TILEB)
#define NSTAGE 3
#define TG_SMEM (NSTAGE * STAGEB)

template<int EPI>
__global__ __launch_bounds__(256, 1)
void tgemm_kernel(const unsigned short* __restrict__ Ahi16,
                  const unsigned short* __restrict__ Alo16,
                  const unsigned short* __restrict__ Whi16,
                  const unsigned short* __restrict__ Wlo16,
                  size_t wz,
                  const float* __restrict__ bias0, const float* __restrict__ bias1,
                  const float* __restrict__ bias2,
                  const float* __restrict__ R,
                  float* __restrict__ C0, float* __restrict__ C1, float* __restrict__ C2,
                  int M, int N, int K)
{
    extern __shared__ __align__(128) char smem[];
    const int z = blockIdx.z;
    const unsigned short* Bh = Whi16 + wz * z;
    const unsigned short* Bl = Wlo16 + wz * z;
    const float* bias = (z == 0) ? bias0 : (z == 1) ? bias1 : bias2;
    float*       C    = (z == 0) ? C0    : (z == 1) ? C1    : C2;

    const uint32_t sbase = smem_u32(smem);
    const int t    = threadIdx.x;
    const int wid  = t >> 5;
    const int lane = t & 31;
    const int m0   = blockIdx.y * 128;
    const int n0   = blockIdx.x * 128;
    const int wm   = (wid & 1) * 64;
    const int wn   = (wid >> 1) * 32;

    const int lrow = t >> 1;
    const int lu   = (t & 1) * 2;
    const unsigned short* pAh = Ahi16 + (size_t)(m0 + lrow) * K + lu * 8;
    const unsigned short* pAl = Alo16 + (size_t)(m0 + lrow) * K + lu * 8;
    const unsigned short* pBh = Bh    + (size_t)(n0 + lrow) * K + lu * 8;
    const unsigned short* pBl = Bl    + (size_t)(n0 + lrow) * K + lu * 8;
    const uint32_t sRow = (uint32_t)lrow * ROWB + lu * 16;

    #define LOAD_STAGE(cc, ss) do {                                        \
        const uint32_t sb_ = sbase + (ss) * STAGEB + sRow;                  \
        const size_t  ko_ = (size_t)(cc) * 32;                              \
        cpa16(sb_ + 0 * TILEB,      pAh + ko_);                             \
        cpa16(sb_ + 0 * TILEB + 16, pAh + ko_ + 8);                         \
        cpa16(sb_ + 1 * TILEB,      pAl + ko_);                             \
        cpa16(sb_ + 1 * TILEB + 16, pAl + ko_ + 8);                         \
        cpa16(sb_ + 2 * TILEB,      pBh + ko_);                             \
        cpa16(sb_ + 2 * TILEB + 16, pBh + ko_ + 8);                         \
        cpa16(sb_ + 3 * TILEB,      pBl + ko_);                             \
        cpa16(sb_ + 3 * TILEB + 16, pBl + ko_ + 8);                         \
    } while (0)

    const uint32_t laneA = (uint32_t)(lane & 15) * ROWB + (lane >> 4) * 16;
    const uint32_t laneB = (uint32_t)((lane & 7) + ((lane >> 4) << 3)) * ROWB
                         + ((lane >> 3) & 1) * 16;

    float acc[4][4][4];
    #pragma unroll
    for (int i = 0; i < 4; ++i)
        #pragma unroll
        for (int j = 0; j < 4; ++j)
            #pragma unroll
            for (int q = 0; q < 4; ++q) acc[i][j][q] = 0.0f;

    const int NC = K >> 5;
    LOAD_STAGE(0, 0); cp_commit();
    LOAD_STAGE(1, 1); cp_commit();
    LOAD_STAGE(2, 2); cp_commit();

    for (int c = 0; c < NC; ++c) {
        const int s = c % NSTAGE;
        cp_wait<NSTAGE - 1>();
        __syncthreads();

        const uint32_t stg = sbase + s * STAGEB;
        #pragma unroll
        for (int ks = 0; ks < 2; ++ks) {
            const uint32_t kb = ks * 32;
            uint32_t ah[4][4], al[4][4], bh[4][2], bl[4][2];
            #pragma unroll
            for (int mf = 0; mf < 4; ++mf) {
                const uint32_t ra = stg + (uint32_t)(wm + mf * 16) * ROWB + laneA + kb;
                ldm_x4(ah[mf], ra + 0 * TILEB);
                ldm_x4(al[mf], ra + 1 * TILEB);
            }
            #pragma unroll
            for (int p = 0; p < 2; ++p) {
                uint32_t rb[4], rl[4];
                const uint32_t ra = stg + (uint32_t)(wn + p * 16) * ROWB + laneB + kb;
                ldm_x4(rb, ra + 2 * TILEB);
                ldm_x4(rl, ra + 3 * TILEB);
                bh[p * 2 + 0][0] = rb[0]; bh[p * 2 + 0][1] = rb[1];
                bh[p * 2 + 1][0] = rb[2]; bh[p * 2 + 1][1] = rb[3];
                bl[p * 2 + 0][0] = rl[0]; bl[p * 2 + 0][1] = rl[1];
                bl[p * 2 + 1][0] = rl[2]; bl[p * 2 + 1][1] = rl[3];
            }
            #pragma unroll
            for (int mf = 0; mf < 4; ++mf)
                #pragma unroll
                for (int nf = 0; nf < 4; ++nf) {
                    mma16816(acc[mf][nf], ah[mf], bh[nf]);
                    mma16816(acc[mf][nf], ah[mf], bl[nf]);
                    mma16816(acc[mf][nf], al[mf], bh[nf]);
                }
        }
        __syncthreads();
        if (c + NSTAGE < NC) LOAD_STAGE(c + NSTAGE, s);
        cp_commit();
    }

    const int rbase = lane >> 2;
    const int cbase = (lane & 3) * 2;
    #pragma unroll
    for (int mf = 0; mf < 4; ++mf) {
        #pragma unroll
        for (int nf = 0; nf < 4; ++nf) {
            const int col = n0 + wn + nf * 8 + cbase;
            const float2 bb = *(const float2*)&bias[col];
            #pragma unroll
            for (int h = 0; h < 2; ++h) {
                const int row = m0 + wm + mf * 16 + rbase + h * 8;
                float2 rv;
                rv.x = acc[mf][nf][h * 2 + 0] + bb.x;
                rv.y = acc[mf][nf][h * 2 + 1] + bb.y;
                if (EPI == 1) { rv.x = gelu_f(rv.x); rv.y = gelu_f(rv.y); }
                if (EPI == 2) {
                    const float2 rr = *(const float2*)&R[(size_t)row * N + col];
                    rv.x += rr.x; rv.y += rr.y;
                }
                *(float2*)&C[(size_t)row * N + col] = rv;
            }
        }
    }
    #undef LOAD_STAGE
}

// ---------------------------------------------------------------------------
// fp32 -> bf16 hi/lo split kernels
// ---------------------------------------------------------------------------
__device__ __forceinline__ void split1(float v, unsigned short& h, unsigned short& l) {
    __nv_bfloat16 hb = __float2bfloat16(v);
    __nv_bfloat16 lb = __float2bfloat16(v - __bfloat162float(hb));
    h = *(unsigned short*)&hb;
    l = *(unsigned short*)&lb;
}

__global__ __launch_bounds__(256)
void split_kernel(const float* __restrict__ X, unsigned short* __restrict__ hi,
                  unsigned short* __restrict__ lo, int n4)
{
    int i = blockIdx.x * 256 + threadIdx.x;
    if (i >= n4) return;
    float4 v = ((const float4*)X)[i];
    ushort4 h, l;
    split1(v.x, h.x, l.x); split1(v.y, h.y, l.y);
    split1(v.z, h.z, l.z); split1(v.w, h.w, l.w);
    ((ushort4*)hi)[i] = h;
    ((ushort4*)lo)[i] = l;
}

__global__ __launch_bounds__(256)
void tsplit_kernel(const float* __restrict__ W, unsigned short* __restrict__ Thi,
                   unsigned short* __restrict__ Tlo, int K, int N)
{
    __shared__ float s[32][33];
    const int tx = threadIdx.x, ty = threadIdx.y;
    const int nb = blockIdx.x * 32, kb = blockIdx.y * 32;
    #pragma unroll
    for (int i = 0; i < 4; ++i)
        s[ty + i * 8][tx] = W[(size_t)(kb + ty + i * 8) * N + nb + tx];
    __syncthreads();
    #pragma unroll
    for (int i = 0; i < 4; ++i) {
        const float v = s[tx][ty + i * 8];
        unsigned short h, l;
        split1(v, h, l);
        const size_t o = (size_t)(nb + ty + i * 8) * K + kb + tx;
        Thi[o] = h; Tlo[o] = l;
    }
}

// ---------------------------------------------------------------------------
// Flash attention via mma.sync (bf16 3-product split, fp32 softmax/accum)
// CTA: 128 queries x 1 batch-head. 8 warps, 16 q-rows each. KV tiles of 64.
// SMEM: Qhi/Qlo [128x64] + 2-stage {Khi,Klo,Vthi,Vtlo}[64x64] + mask bias.
// ---------------------------------------------------------------------------
#define AROWB   144
#define ATT_QLO 18432                 // 128*144
#define ATT_KV  36864
#define ATT_STG 36864                 // 4 tiles * 64*144
#define ATT_MB  (ATT_KV + 2 * ATT_STG)
#define ATT_SMEM (ATT_MB + 512)

__global__ __launch_bounds__(256, 1)
void attn_mma_kernel(const unsigned short* __restrict__ Qhi,
                     const unsigned short* __restrict__ Qlo,
                     const unsigned short* __restrict__ Khi,
                     const unsigned short* __restrict__ Klo,
                     const unsigned short* __restrict__ Vthi,
                     const unsigned short* __restrict__ Vtlo,
                     const int* __restrict__ mask,
                     float* __restrict__ Y)
{
    extern __shared__ __align__(128) char smem[];
    const uint32_t sb = smem_u32(smem);
    const int t    = threadIdx.x;
    const int lane = t & 31;
    const int w    = t >> 5;
    const int q0   = blockIdx.x * 128;
    const int bh   = blockIdx.y;
    const int tokb = (bh >> 4) * 2048;
    const int colb = (bh & 15) * 64;

    const uint32_t laneA = (uint32_t)(lane & 15) * AROWB + (lane >> 4) * 16;
    const uint32_t laneB = (uint32_t)((lane & 7) + ((lane >> 4) << 3)) * AROWB
                         + ((lane >> 3) & 1) * 16;

    // ---- Q tile loads (once) ----
    {
        const int row = t >> 1;
        const size_t g = (size_t)(tokb + q0 + row) * 1024 + colb;
        const uint32_t sr = (uint32_t)row * AROWB;
        #pragma unroll
        for (int i = 0; i < 4; ++i) {
            const int ch = (t & 1) * 4 + i;
            cpa16(sb + sr + ch * 16,           Qhi + g + ch * 8);
            cpa16(sb + ATT_QLO + sr + ch * 16, Qlo + g + ch * 8);
        }
    }

    // ---- KV tile loader ----
    auto LOADKV = [&](int tile, int s) {
        const int kv0 = tile * 64;
        const int row = t >> 2;
        const int q2  = t & 3;
        const uint32_t st = sb + ATT_KV + s * ATT_STG;
        const size_t gk = (size_t)(tokb + kv0 + row) * 1024 + colb;
        const size_t gv = (size_t)(colb + row) * 4096 + tokb + kv0;
        const uint32_t sr = (uint32_t)row * AROWB;
        #pragma unroll
        for (int i = 0; i < 2; ++i) {
            const int ch = q2 * 2 + i;
            cpa16(st +         sr + ch * 16, Khi  + gk + ch * 8);
            cpa16(st +  9216 + sr + ch * 16, Klo  + gk + ch * 8);
            cpa16(st + 18432 + sr + ch * 16, Vthi + gv + ch * 8);
            cpa16(st + 27648 + sr + ch * 16, Vtlo + gv + ch * 8);
        }
        if (t < 64) {
            float* mb = (float*)(smem + ATT_MB) + s * 64;
            mb[t] = (mask[tokb + kv0 + t] == 0) ? -1e30f : 0.0f;
        }
    };

    LOADKV(0, 0); cp_commit();
    LOADKV(1, 1); cp_commit();

    cp_wait<1>();
    __syncthreads();

    // ---- persistent Q fragments ----
    uint32_t qh[4][4], ql[4][4];
    #pragma unroll
    for (int fk = 0; fk < 4; ++fk) {
        const uint32_t ra = sb + (uint32_t)(w * 16) * AROWB + laneA + fk * 32;
        ldm_x4(qh[fk], ra);
        ldm_x4(ql[fk], ra + ATT_QLO);
    }

    float of[8][4];
    #pragma unroll
    for (int i = 0; i < 8; ++i)
        #pragma unroll
        for (int j = 0; j < 4; ++j) of[i][j] = 0.0f;
    float mA = -1e30f, mB = -1e30f, lA = 0.0f, lB = 0.0f;
    const int c0 = (lane & 3) * 2;

    for (int tile = 0; tile < 32; ++tile) {
        const int s = tile & 1;
        if (tile > 0) { cp_wait<1>(); __syncthreads(); }
        const uint32_t kst = sb + ATT_KV + s * ATT_STG;
        const float* mb = (const float*)(smem + ATT_MB) + s * 64;

        // ---- S = (Qhi+Qlo)(Khi+Klo)^T, 3-product ----
        float sf[8][4];
        #pragma unroll
        for (int i = 0; i < 8; ++i)
            #pragma unroll
            for (int j = 0; j < 4; ++j) sf[i][j] = 0.0f;

        #pragma unroll
        for (int fk = 0; fk < 4; ++fk) {
            uint32_t kh[8][2], kl[8][2];
            #pragma unroll
            for (int p = 0; p < 4; ++p) {
                uint32_t r0[4], r1[4];
                const uint32_t ra = kst + (uint32_t)(p * 16) * AROWB + laneB + fk * 32;
                ldm_x4(r0, ra);
                ldm_x4(r1, ra + 9216);
                kh[p * 2 + 0][0] = r0[0]; kh[p * 2 + 0][1] = r0[1];
                kh[p * 2 + 1][0] = r0[2]; kh[p * 2 + 1][1] = r0[3];
                kl[p * 2 + 0][0] = r1[0]; kl[p * 2 + 0][1] = r1[1];
                kl[p * 2 + 1][0] = r1[2]; kl[p * 2 + 1][1] = r1[3];
            }
            #pragma unroll
            for (int nf = 0; nf < 8; ++nf) {
                mma16816(sf[nf], qh[fk], kh[nf]);
                mma16816(sf[nf], qh[fk], kl[nf]);
                mma16816(sf[nf], ql[fk], kh[nf]);
            }
        }

        // ---- online softmax (rows rA = lane>>2, rB = rA+8) ----
        float pmA = -1e30f, pmB = -1e30f;
        #pragma unroll
        for (int nf = 0; nf < 8; ++nf) {
            const float m0 = mb[nf * 8 + c0];
            const float m1 = mb[nf * 8 + c0 + 1];
            sf[nf][0] = fmaf(sf[nf][0], 0.125f, m0);
            sf[nf][1] = fmaf(sf[nf][1], 0.125f, m1);
            sf[nf][2] = fmaf(sf[nf][2], 0.125f, m0);
            sf[nf][3] = fmaf(sf[nf][3], 0.125f, m1);
            pmA = fmaxf(pmA, fmaxf(sf[nf][0], sf[nf][1]));
            pmB = fmaxf(pmB, fmaxf(sf[nf][2], sf[nf][3]));
        }
        pmA = fmaxf(pmA, __shfl_xor_sync(0xffffffffu, pmA, 1));
        pmA = fmaxf(pmA, __shfl_xor_sync(0xffffffffu, pmA, 2));
        pmB = fmaxf(pmB, __shfl_xor_sync(0xffffffffu, pmB, 1));
        pmB = fmaxf(pmB, __shfl_xor_sync(0xffffffffu, pmB, 2));
        const float mnA = fmaxf(mA, pmA), mnB = fmaxf(mB, pmB);
        const float alA = __expf(mA - mnA), alB = __expf(mB - mnB);
        mA = mnA; mB = mnB;
        float rsA = 0.0f, rsB = 0.0f;
        #pragma unroll
        for (int nf = 0; nf < 8; ++nf) {
            sf[nf][0] = __expf(sf[nf][0] - mnA);
            sf[nf][1] = __expf(sf[nf][1] - mnA);
            sf[nf][2] = __expf(sf[nf][2] - mnB);
            sf[nf][3] = __expf(sf[nf][3] - mnB);
            rsA += sf[nf][0] + sf[nf][1];
            rsB += sf[nf][2] + sf[nf][3];
        }
        rsA += __shfl_xor_sync(0xffffffffu, rsA, 1);
        rsA += __shfl_xor_sync(0xffffffffu, rsA, 2);
        rsB += __shfl_xor_sync(0xffffffffu, rsB, 1);
        rsB += __shfl_xor_sync(0xffffffffu, rsB, 2);
        lA = lA * alA + rsA;
        lB = lB * alB + rsB;
        #pragma unroll
        for (int nf = 0; nf < 8; ++nf) {
            of[nf][0] *= alA; of[nf][1] *= alA;
            of[nf][2] *= alB; of[nf][3] *= alB;
        }

        // ---- O += (Phi+Plo) (Vthi+Vtlo)^T, 3-product ----
        #pragma unroll
        for (int fk = 0; fk < 4; ++fk) {
            uint32_t aHi[4], aLo[4];
            bfsplit2(sf[2 * fk][0],     sf[2 * fk][1],     aHi[0], aLo[0]);
            bfsplit2(sf[2 * fk][2],     sf[2 * fk][3],     aHi[1], aLo[1]);
            bfsplit2(sf[2 * fk + 1][0], sf[2 * fk + 1][1], aHi[2], aLo[2]);
            bfsplit2(sf[2 * fk + 1][2], sf[2 * fk + 1][3], aHi[3], aLo[3]);
            uint32_t vh[8][2], vl[8][2];
            #pragma unroll
            for (int p = 0; p < 4; ++p) {
                uint32_t r0[4], r1[4];
                const uint32_t ra = kst + 18432 + (uint32_t)(p * 16) * AROWB + laneB + fk * 32;
                ldm_x4(r0, ra);
                ldm_x4(r1, ra + 9216);
                vh[p * 2 + 0][0] = r0[0]; vh[p * 2 + 0][1] = r0[1];
                vh[p * 2 + 1][0] = r0[2]; vh[p * 2 + 1][1] = r0[3];
                vl[p * 2 + 0][0] = r1[0]; vl[p * 2 + 0][1] = r1[1];
                vl[p * 2 + 1][0] = r1[2]; vl[p * 2 + 1][1] = r1[3];
            }
            #pragma unroll
            for (int nf = 0; nf < 8; ++nf) {
                mma16816(of[nf], aHi, vh[nf]);
                mma16816(of[nf], aHi, vl[nf]);
                mma16816(of[nf], aLo, vh[nf]);
            }
        }

        __syncthreads();
        if (tile + 2 < 32) LOADKV(tile + 2, s);
        cp_commit();
    }

    // ---- write O ----
    const float iA = 1.0f / lA, iB = 1.0f / lB;
    const int rA = lane >> 2;
    const int rowA = tokb + q0 + w * 16 + rA;
    #pragma unroll
    for (int nf = 0; nf < 8; ++nf) {
        const int col = colb + nf * 8 + c0;
        float2 oa, ob;
        oa.x = of[nf][0] * iA; oa.y = of[nf][1] * iA;
        ob.x = of[nf][2] * iB; ob.y = of[nf][3] * iB;
        *(float2*)&Y[(size_t)rowA * 1024 + col]       = oa;
        *(float2*)&Y[(size_t)(rowA + 8) * 1024 + col] = ob;
    }
}

// ---------------------------------------------------------------------------
// LayerNorm: one row (1024) per CTA
// ---------------------------------------------------------------------------
__global__ __launch_bounds__(256)
void ln_kernel(const float* __restrict__ X, const float* __restrict__ w,
               const float* __restrict__ b, float* __restrict__ out)
{
    __shared__ float red[2][8];
    const int t = threadIdx.x;
    const size_t row = blockIdx.x;
    float4 xv = *(const float4*)&X[row * 1024 + t * 4];
    float s  = xv.x + xv.y + xv.z + xv.w;
    float s2 = xv.x * xv.x + xv.y * xv.y + xv.z * xv.z + xv.w * xv.w;
    #pragma unroll
    for (int off = 16; off; off >>= 1) {
        s  += __shfl_xor_sync(0xffffffffu, s,  off);
        s2 += __shfl_xor_sync(0xffffffffu, s2, off);
    }
    if ((t & 31) == 0) { red[0][t >> 5] = s; red[1][t >> 5] = s2; }
    __syncthreads();
    float S = 0.0f, S2 = 0.0f;
    #pragma unroll
    for (int i = 0; i < 8; ++i) { S += red[0][i]; S2 += red[1][i]; }
    const float mean = S * (1.0f / 1024.0f);
    const float var  = S2 * (1.0f / 1024.0f) - mean * mean;
    const float rstd = rsqrtf(var + 1e-5f);
    float4 wv = *(const float4*)&w[t * 4];
    float4 bv = *(const float4*)&b[t * 4];
    float4 r;
    r.x = (xv.x - mean) * rstd * wv.x + bv.x;
    r.y = (xv.y - mean) * rstd * wv.y + bv.y;
    r.z = (xv.z - mean) * rstd * wv.z + bv.z;
    r.w = (xv.w - mean) * rstd * wv.w + bv.w;
    *(float4*)&out[row * 1024 + t * 4] = r;
}

// ---------------------------------------------------------------------------
// launch
// ---------------------------------------------------------------------------
extern "C" void kernel_launch(void* const* d_in, const int* in_sizes, int n_in,
                              void* d_out, int out_size)
{
    (void)in_sizes; (void)n_in; (void)out_size;
    const float* x    = (const float*)d_in[0];
    const int*   mask = (const int*)  d_in[1];
    const float* WQ   = (const float*)d_in[2];
    const float* bQ   = (const float*)d_in[3];
    const float* WK   = (const float*)d_in[4];
    const float* bK   = (const float*)d_in[5];
    const float* WV   = (const float*)d_in[6];
    const float* bV   = (const float*)d_in[7];
    const float* WY   = (const float*)d_in[8];
    const float* bY   = (const float*)d_in[9];
    const float* ln1w = (const float*)d_in[10];
    const float* ln1b = (const float*)d_in[11];
    const float* ln2w = (const float*)d_in[12];
    const float* ln2b = (const float*)d_in[13];
    const float* W1   = (const float*)d_in[14];
    const float* b1   = (const float*)d_in[15];
    const float* W2   = (const float*)d_in[16];
    const float* b2   = (const float*)d_in[17];
    float* out = (float*)d_out;

    float *Qp, *Kp, *Vp, *Yp, *FFp;
    unsigned short *Ahi, *Alo, *Whi, *Wlo;
    unsigned short *Qhi, *Qlo, *Khi, *Klo, *Vthi, *Vtlo;
    cudaGetSymbolAddress((void**)&Qp,  g_Q);
    cudaGetSymbolAddress((void**)&Kp,  g_K);
    cudaGetSymbolAddress((void**)&Vp,  g_V);
    cudaGetSymbolAddress((void**)&Yp,  g_Y);
    cudaGetSymbolAddress((void**)&FFp, g_FF);
    cudaGetSymbolAddress((void**)&Ahi, g_Ahi);
    cudaGetSymbolAddress((void**)&Alo, g_Alo);
    cudaGetSymbolAddress((void**)&Whi, g_Whi);
    cudaGetSymbolAddress((void**)&Wlo, g_Wlo);
    cudaGetSymbolAddress((void**)&Qhi,  g_Qhi);
    cudaGetSymbolAddress((void**)&Qlo,  g_Qlo);
    cudaGetSymbolAddress((void**)&Khi,  g_Khi);
    cudaGetSymbolAddress((void**)&Klo,  g_Klo);
    cudaGetSymbolAddress((void**)&Vthi, g_Vthi);
    cudaGetSymbolAddress((void**)&Vtlo, g_Vtlo);

    const size_t MB = (size_t)1024 * 1024;

    cudaFuncSetAttribute(tgemm_kernel<0>,
                         cudaFuncAttributeMaxDynamicSharedMemorySize, TG_SMEM);
    cudaFuncSetAttribute(tgemm_kernel<1>,
                         cudaFuncAttributeMaxDynamicSharedMemorySize, TG_SMEM);
    cudaFuncSetAttribute(tgemm_kernel<2>,
                         cudaFuncAttributeMaxDynamicSharedMemorySize, TG_SMEM);
    cudaFuncSetAttribute(attn_mma_kernel,
                         cudaFuncAttributeMaxDynamicSharedMemorySize, ATT_SMEM);

    dim3 blk(256);
    dim3 tsb(32, 8);

    // weight transpose + split
    tsplit_kernel<<<dim3(32, 32),  tsb>>>(WQ, Whi + 0 * MB, Wlo + 0 * MB, 1024, 1024);
    tsplit_kernel<<<dim3(32, 32),  tsb>>>(WK, Whi + 1 * MB, Wlo + 1 * MB, 1024, 1024);
    tsplit_kernel<<<dim3(32, 32),  tsb>>>(WV, Whi + 2 * MB, Wlo + 2 * MB, 1024, 1024);
    tsplit_kernel<<<dim3(32, 32),  tsb>>>(WY, Whi + 3 * MB, Wlo + 3 * MB, 1024, 1024);
    tsplit_kernel<<<dim3(128, 32), tsb>>>(W1, Whi + 4 * MB, Wlo + 4 * MB, 1024, 4096);
    tsplit_kernel<<<dim3(32, 128), tsb>>>(W2, Whi + 8 * MB, Wlo + 8 * MB, 4096, 1024);

    // x split
    split_kernel<<<4096, blk>>>(x, Ahi, Alo, (4096 * 1024) / 4);

    // QKV projections (fused z)
    tgemm_kernel<0><<<dim3(8, 32, 3), blk, TG_SMEM>>>(
        Ahi, Alo, Whi, Wlo, MB, bQ, bK, bV, nullptr, Qp, Kp, Vp, 4096, 1024, 1024);

    // attention operand prep: Q/K row-major split, V transposed split
    split_kernel<<<4096, blk>>>(Qp, Qhi, Qlo, (4096 * 1024) / 4);
    split_kernel<<<4096, blk>>>(Kp, Khi, Klo, (4096 * 1024) / 4);
    tsplit_kernel<<<dim3(32, 128), tsb>>>(Vp, Vthi, Vtlo, 4096, 1024);

    // attention -> g_Y
    attn_mma_kernel<<<dim3(16, 32), blk, ATT_SMEM>>>(
        Qhi, Qlo, Khi, Klo, Vthi, Vtlo, mask, Yp);

    // out-proj + residual x -> g_Q
    split_kernel<<<4096, blk>>>(Yp, Ahi, Alo, (4096 * 1024) / 4);
    tgemm_kernel<2><<<dim3(8, 32, 1), blk, TG_SMEM>>>(
        Ahi, Alo, Whi + 3 * MB, Wlo + 3 * MB, 0, bY, bY, bY, x, Qp, Qp, Qp,
        4096, 1024, 1024);

    // h = LN1 -> g_K
    ln_kernel<<<4096, blk>>>(Qp, ln1w, ln1b, Kp);

    // FFN1: gelu(h@W1+b1) -> g_FF
    split_kernel<<<4096, blk>>>(Kp, Ahi, Alo, (4096 * 1024) / 4);
    tgemm_kernel<1><<<dim3(32, 32, 1), blk, TG_SMEM>>>(
        Ahi, Alo, Whi + 4 * MB, Wlo + 4 * MB, 0, b1, b1, b1, nullptr, FFp, FFp, FFp,
        4096, 4096, 1024);

    // FFN2: ff@W2+b2+h -> g_V
    split_kernel<<<16384, blk>>>(FFp, Ahi, Alo, (4096 * 4096) / 4);
    tgemm_kernel<2><<<dim3(8, 32, 1), blk, TG_SMEM>>>(
        Ahi, Alo, Whi + 8 * MB, Wlo + 8 * MB, 0, b2, b2, b2, Kp, Vp, Vp, Vp,
        4096, 1024, 4096);

    // out = LN2
    ln_kernel<<<4096, blk>>>(Vp, ln2w, ln2b, out);
}

// round 6
// speedup vs baseline: 2.1269x; 1.0292x over previous
#include <cuda_runtime.h>
#include <cuda_bf16.h>
#include <math.h>
#include <stdint.h>

// ---------------------------------------------------------------------------
// Scratch (__device__ globals; no allocations allowed)
// ---------------------------------------------------------------------------
__device__ float g_Q [(size_t)4096 * 1024];   // out-proj result (a+x)
__device__ float g_K [(size_t)4096 * 1024];   // h = LN1(...)
__device__ float g_V [(size_t)4096 * 1024];   // V fp32, later ffn2 result
__device__ float g_Y [(size_t)4096 * 1024];   // holds Yhi/Ylo bf16 halves
__device__ unsigned short g_Ahi[(size_t)4096 * 4096];  // x split, later FF split hi
__device__ unsigned short g_Alo[(size_t)4096 * 4096];  // x split, later FF split lo
__device__ unsigned short g_Whi[(size_t)12 * 1024 * 1024];
__device__ unsigned short g_Wlo[(size_t)12 * 1024 * 1024];
__device__ unsigned short g_Qhi [(size_t)4096 * 1024]; // Q split, later h split hi
__device__ unsigned short g_Qlo [(size_t)4096 * 1024];
__device__ unsigned short g_Khi [(size_t)4096 * 1024];
__device__ unsigned short g_Klo [(size_t)4096 * 1024];
__device__ unsigned short g_Vthi[(size_t)1024 * 4096];
__device__ unsigned short g_Vtlo[(size_t)1024 * 4096];

__device__ __forceinline__ uint32_t smem_u32(const void* p) {
    uint32_t a;
    asm("{ .reg .u64 t; cvta.to.shared.u64 t, %1; cvt.u32.u64 %0, t; }"
        : "=r"(a) : "l"(p));
    return a;
}
__device__ __forceinline__ void cpa16(uint32_t s, const void* g) {
    asm volatile("cp.async.cg.shared.global [%0], [%1], 16;"
                 :: "r"(s), "l"(__cvta_generic_to_global(g)) : "memory");
}
__device__ __forceinline__ void cp_commit() {
    asm volatile("cp.async.commit_group;" ::: "memory");
}
template<int N>
__device__ __forceinline__ void cp_wait() {
    asm volatile("cp.async.wait_group %0;" :: "n"(N) : "memory");
}
__device__ __forceinline__ void ldm_x4(uint32_t* r, uint32_t saddr) {
    asm volatile("ldmatrix.sync.aligned.m8n8.x4.shared.b16 {%0,%1,%2,%3}, [%4];"
                 : "=r"(r[0]), "=r"(r[1]), "=r"(r[2]), "=r"(r[3]) : "r"(saddr));
}
__device__ __forceinline__ void mma16816(float* c, const uint32_t* a, const uint32_t* b) {
    asm volatile("mma.sync.aligned.m16n8k16.row.col.f32.bf16.bf16.f32 "
                 "{%0,%1,%2,%3}, {%4,%5,%6,%7}, {%8,%9}, {%0,%1,%2,%3};"
                 : "+f"(c[0]), "+f"(c[1]), "+f"(c[2]), "+f"(c[3])
                 : "r"(a[0]), "r"(a[1]), "r"(a[2]), "r"(a[3]),
                   "r"(b[0]), "r"(b[1]));
}
__device__ __forceinline__ float gelu_f(float v) {
    return 0.5f * v * (1.0f + erff(v * 0.70710678118654752f));
}
__device__ __forceinline__ void bfsplit2(float x, float y, uint32_t& hi, uint32_t& lo) {
    __nv_bfloat16 hx = __float2bfloat16(x), hy = __float2bfloat16(y);
    hi = ((uint32_t)(*(unsigned short*)&hy) << 16) | (uint32_t)(*(unsigned short*)&hx);
    __nv_bfloat16 lx = __float2bfloat16(x - __bfloat162float(hx));
    __nv_bfloat16 ly = __float2bfloat16(y - __bfloat162float(hy));
    lo = ((uint32_t)(*(unsigned short*)&ly) << 16) | (uint32_t)(*(unsigned short*)&lx);
}

// ---------------------------------------------------------------------------
// Tensor-core dense GEMM, single-sync 3-stage pipeline, fused split outputs.
// C = (Ahi+Alo)[M,K] @ (Whi+Wlo)[N,K]^T (+bias | +bias,gelu | +bias+residual)
// Outputs per z: optional fp32 Cf, optional bf16 hi/lo pair (Ch/Cl).
// ---------------------------------------------------------------------------
#define ROWB   80
#define TILEB  (128 * ROWB)
#define STAGEB (4 * TILEB)
#define NSTAGE 3
#define TG_SMEM (NSTAGE * STAGEB)

template<int EPI>
__global__ __launch_bounds__(256, 1)
void tgemm_kernel(const unsigned short* __restrict__ Ahi16,
                  const unsigned short* __restrict__ Alo16,
                  const unsigned short* __restrict__ Whi16,
                  const unsigned short* __restrict__ Wlo16,
                  size_t wz,
                  const float* __restrict__ bias0, const float* __restrict__ bias1,
                  const float* __restrict__ bias2,
                  const float* __restrict__ R,
                  float* __restrict__ Cf0, float* __restrict__ Cf1, float* __restrict__ Cf2,
                  unsigned short* __restrict__ Ch0, unsigned short* __restrict__ Ch1,
                  unsigned short* __restrict__ Ch2,
                  unsigned short* __restrict__ Cl0, unsigned short* __restrict__ Cl1,
                  unsigned short* __restrict__ Cl2,
                  int M, int N, int K)
{
    extern __shared__ __align__(128) char smem[];
    const int z = blockIdx.z;
    const unsigned short* Bh = Whi16 + wz * z;
    const unsigned short* Bl = Wlo16 + wz * z;
    const float* bias = (z == 0) ? bias0 : (z == 1) ? bias1 : bias2;
    float*          Cf = (z == 0) ? Cf0 : (z == 1) ? Cf1 : Cf2;
    unsigned short* Ch = (z == 0) ? Ch0 : (z == 1) ? Ch1 : Ch2;
    unsigned short* Cl = (z == 0) ? Cl0 : (z == 1) ? Cl1 : Cl2;

    const uint32_t sbase = smem_u32(smem);
    const int t    = threadIdx.x;
    const int wid  = t >> 5;
    const int lane = t & 31;
    const int m0   = blockIdx.y * 128;
    const int n0   = blockIdx.x * 128;
    const int wm   = (wid & 1) * 64;
    const int wn   = (wid >> 1) * 32;

    const int lrow = t >> 1;
    const int lu   = (t & 1) * 2;
    const unsigned short* pAh = Ahi16 + (size_t)(m0 + lrow) * K + lu * 8;
    const unsigned short* pAl = Alo16 + (size_t)(m0 + lrow) * K + lu * 8;
    const unsigned short* pBh = Bh    + (size_t)(n0 + lrow) * K + lu * 8;
    const unsigned short* pBl = Bl    + (size_t)(n0 + lrow) * K + lu * 8;
    const uint32_t sRow = (uint32_t)lrow * ROWB + lu * 16;

    #define LOAD_STAGE(cc, ss) do {                                        \
        const uint32_t sb_ = sbase + (ss) * STAGEB + sRow;                  \
        const size_t  ko_ = (size_t)(cc) * 32;                              \
        cpa16(sb_ + 0 * TILEB,      pAh + ko_);                             \
        cpa16(sb_ + 0 * TILEB + 16, pAh + ko_ + 8);                         \
        cpa16(sb_ + 1 * TILEB,      pAl + ko_);                             \
        cpa16(sb_ + 1 * TILEB + 16, pAl + ko_ + 8);                         \
        cpa16(sb_ + 2 * TILEB,      pBh + ko_);                             \
        cpa16(sb_ + 2 * TILEB + 16, pBh + ko_ + 8);                         \
        cpa16(sb_ + 3 * TILEB,      pBl + ko_);                             \
        cpa16(sb_ + 3 * TILEB + 16, pBl + ko_ + 8);                         \
    } while (0)

    const uint32_t laneA = (uint32_t)(lane & 15) * ROWB + (lane >> 4) * 16;
    const uint32_t laneB = (uint32_t)((lane & 7) + ((lane >> 4) << 3)) * ROWB
                         + ((lane >> 3) & 1) * 16;

    float acc[4][4][4];
    #pragma unroll
    for (int i = 0; i < 4; ++i)
        #pragma unroll
        for (int j = 0; j < 4; ++j)
            #pragma unroll
            for (int q = 0; q < 4; ++q) acc[i][j][q] = 0.0f;

    const int NC = K >> 5;
    // prologue: 2 of 3 stages in flight
    LOAD_STAGE(0, 0); cp_commit();
    LOAD_STAGE(1, 1); cp_commit();

    for (int c = 0; c < NC; ++c) {
        const int s = c % NSTAGE;
        cp_wait<1>();
        __syncthreads();
        // issue loads for chunk c+2 into the slot freed at iter c-1
        if (c + 2 < NC) LOAD_STAGE(c + 2, (c + 2) % NSTAGE);
        cp_commit();

        const uint32_t stg = sbase + s * STAGEB;
        #pragma unroll
        for (int ks = 0; ks < 2; ++ks) {
            const uint32_t kb = ks * 32;
            uint32_t ah[4][4], al[4][4], bh[4][2], bl[4][2];
            #pragma unroll
            for (int mf = 0; mf < 4; ++mf) {
                const uint32_t ra = stg + (uint32_t)(wm + mf * 16) * ROWB + laneA + kb;
                ldm_x4(ah[mf], ra + 0 * TILEB);
                ldm_x4(al[mf], ra + 1 * TILEB);
            }
            #pragma unroll
            for (int p = 0; p < 2; ++p) {
                uint32_t rb[4], rl[4];
                const uint32_t ra = stg + (uint32_t)(wn + p * 16) * ROWB + laneB + kb;
                ldm_x4(rb, ra + 2 * TILEB);
                ldm_x4(rl, ra + 3 * TILEB);
                bh[p * 2 + 0][0] = rb[0]; bh[p * 2 + 0][1] = rb[1];
                bh[p * 2 + 1][0] = rb[2]; bh[p * 2 + 1][1] = rb[3];
                bl[p * 2 + 0][0] = rl[0]; bl[p * 2 + 0][1] = rl[1];
                bl[p * 2 + 1][0] = rl[2]; bl[p * 2 + 1][1] = rl[3];
            }
            #pragma unroll
            for (int mf = 0; mf < 4; ++mf)
                #pragma unroll
                for (int nf = 0; nf < 4; ++nf) {
                    mma16816(acc[mf][nf], ah[mf], bh[nf]);
                    mma16816(acc[mf][nf], ah[mf], bl[nf]);
                    mma16816(acc[mf][nf], al[mf], bh[nf]);
                }
        }
    }

    // epilogue: fused bias / gelu / residual; fp32 and/or bf16-split outputs
    const int rbase = lane >> 2;
    const int cbase = (lane & 3) * 2;
    #pragma unroll
    for (int mf = 0; mf < 4; ++mf) {
        #pragma unroll
        for (int nf = 0; nf < 4; ++nf) {
            const int col = n0 + wn + nf * 8 + cbase;
            const float2 bb = *(const float2*)&bias[col];
            #pragma unroll
            for (int h = 0; h < 2; ++h) {
                const int row = m0 + wm + mf * 16 + rbase + h * 8;
                float2 rv;
                rv.x = acc[mf][nf][h * 2 + 0] + bb.x;
                rv.y = acc[mf][nf][h * 2 + 1] + bb.y;
                if (EPI == 1) { rv.x = gelu_f(rv.x); rv.y = gelu_f(rv.y); }
                if (EPI == 2) {
                    const float2 rr = *(const float2*)&R[(size_t)row * N + col];
                    rv.x += rr.x; rv.y += rr.y;
                }
                if (Cf) *(float2*)&Cf[(size_t)row * N + col] = rv;
                if (Ch) {
                    uint32_t hi, lo;
                    bfsplit2(rv.x, rv.y, hi, lo);
                    *(uint32_t*)&Ch[(size_t)row * N + col] = hi;
                    *(uint32_t*)&Cl[(size_t)row * N + col] = lo;
                }
            }
        }
    }
    #undef LOAD_STAGE
}

// ---------------------------------------------------------------------------
// fp32 -> bf16 hi/lo split kernels
// ---------------------------------------------------------------------------
__device__ __forceinline__ void split1(float v, unsigned short& h, unsigned short& l) {
    __nv_bfloat16 hb = __float2bfloat16(v);
    __nv_bfloat16 lb = __float2bfloat16(v - __bfloat162float(hb));
    h = *(unsigned short*)&hb;
    l = *(unsigned short*)&lb;
}

__global__ __launch_bounds__(256)
void split_kernel(const float* __restrict__ X, unsigned short* __restrict__ hi,
                  unsigned short* __restrict__ lo, int n4)
{
    int i = blockIdx.x * 256 + threadIdx.x;
    if (i >= n4) return;
    float4 v = ((const float4*)X)[i];
    ushort4 h, l;
    split1(v.x, h.x, l.x); split1(v.y, h.y, l.y);
    split1(v.z, h.z, l.z); split1(v.w, h.w, l.w);
    ((ushort4*)hi)[i] = h;
    ((ushort4*)lo)[i] = l;
}

// transpose+split; z-fused for up to 4 equal-shaped weights
__global__ __launch_bounds__(256)
void tsplit_kernel(const float* __restrict__ W0, const float* __restrict__ W1,
                   const float* __restrict__ W2, const float* __restrict__ W3,
                   unsigned short* __restrict__ Thi, unsigned short* __restrict__ Tlo,
                   size_t zstride, int K, int N)
{
    __shared__ float s[32][33];
    const int z = blockIdx.z;
    const float* W = (z == 0) ? W0 : (z == 1) ? W1 : (z == 2) ? W2 : W3;
    unsigned short* Th = Thi + zstride * z;
    unsigned short* Tl = Tlo + zstride * z;
    const int tx = threadIdx.x, ty = threadIdx.y;
    const int nb = blockIdx.x * 32, kb = blockIdx.y * 32;
    #pragma unroll
    for (int i = 0; i < 4; ++i)
        s[ty + i * 8][tx] = W[(size_t)(kb + ty + i * 8) * N + nb + tx];
    __syncthreads();
    #pragma unroll
    for (int i = 0; i < 4; ++i) {
        const float v = s[tx][ty + i * 8];
        unsigned short h, l;
        split1(v, h, l);
        const size_t o = (size_t)(nb + ty + i * 8) * K + kb + tx;
        Th[o] = h; Tl[o] = l;
    }
}

// ---------------------------------------------------------------------------
// Flash attention via mma.sync; output written directly as bf16 hi/lo
// ---------------------------------------------------------------------------
#define AROWB   144
#define ATT_QLO 18432
#define ATT_KV  36864
#define ATT_STG 36864
#define ATT_MB  (ATT_KV + 2 * ATT_STG)
#define ATT_SMEM (ATT_MB + 512)

__global__ __launch_bounds__(256, 1)
void attn_mma_kernel(const unsigned short* __restrict__ Qhi,
                     const unsigned short* __restrict__ Qlo,
                     const unsigned short* __restrict__ Khi,
                     const unsigned short* __restrict__ Klo,
                     const unsigned short* __restrict__ Vthi,
                     const unsigned short* __restrict__ Vtlo,
                     const int* __restrict__ mask,
                     unsigned short* __restrict__ Yhi,
                     unsigned short* __restrict__ Ylo)
{
    extern __shared__ __align__(128) char smem[];
    const uint32_t sb = smem_u32(smem);
    const int t    = threadIdx.x;
    const int lane = t & 31;
    const int w    = t >> 5;
    const int q0   = blockIdx.x * 128;
    const int bh   = blockIdx.y;
    const int tokb = (bh >> 4) * 2048;
    const int colb = (bh & 15) * 64;

    const uint32_t laneA = (uint32_t)(lane & 15) * AROWB + (lane >> 4) * 16;
    const uint32_t laneB = (uint32_t)((lane & 7) + ((lane >> 4) << 3)) * AROWB
                         + ((lane >> 3) & 1) * 16;

    {
        const int row = t >> 1;
        const size_t g = (size_t)(tokb + q0 + row) * 1024 + colb;
        const uint32_t sr = (uint32_t)row * AROWB;
        #pragma unroll
        for (int i = 0; i < 4; ++i) {
            const int ch = (t & 1) * 4 + i;
            cpa16(sb + sr + ch * 16,           Qhi + g + ch * 8);
            cpa16(sb + ATT_QLO + sr + ch * 16, Qlo + g + ch * 8);
        }
    }

    auto LOADKV = [&](int tile, int s) {
        const int kv0 = tile * 64;
        const int row = t >> 2;
        const int q2  = t & 3;
        const uint32_t st = sb + ATT_KV + s * ATT_STG;
        const size_t gk = (size_t)(tokb + kv0 + row) * 1024 + colb;
        const size_t gv = (size_t)(colb + row) * 4096 + tokb + kv0;
        const uint32_t sr = (uint32_t)row * AROWB;
        #pragma unroll
        for (int i = 0; i < 2; ++i) {
            const int ch = q2 * 2 + i;
            cpa16(st +         sr + ch * 16, Khi  + gk + ch * 8);
            cpa16(st +  9216 + sr + ch * 16, Klo  + gk + ch * 8);
            cpa16(st + 18432 + sr + ch * 16, Vthi + gv + ch * 8);
            cpa16(st + 27648 + sr + ch * 16, Vtlo + gv + ch * 8);
        }
        if (t < 64) {
            float* mb = (float*)(smem + ATT_MB) + s * 64;
            mb[t] = (mask[tokb + kv0 + t] == 0) ? -1e30f : 0.0f;
        }
    };

    LOADKV(0, 0); cp_commit();
    LOADKV(1, 1); cp_commit();

    cp_wait<1>();
    __syncthreads();

    uint32_t qh[4][4], ql[4][4];
    #pragma unroll
    for (int fk = 0; fk < 4; ++fk) {
        const uint32_t ra = sb + (uint32_t)(w * 16) * AROWB + laneA + fk * 32;
        ldm_x4(qh[fk], ra);
        ldm_x4(ql[fk], ra + ATT_QLO);
    }

    float of[8][4];
    #pragma unroll
    for (int i = 0; i < 8; ++i)
        #pragma unroll
        for (int j = 0; j < 4; ++j) of[i][j] = 0.0f;
    float mA = -1e30f, mB = -1e30f, lA = 0.0f, lB = 0.0f;
    const int c0 = (lane & 3) * 2;

    for (int tile = 0; tile < 32; ++tile) {
        const int s = tile & 1;
        if (tile > 0) { cp_wait<1>(); __syncthreads(); }
        const uint32_t kst = sb + ATT_KV + s * ATT_STG;
        const float* mb = (const float*)(smem + ATT_MB) + s * 64;

        float sf[8][4];
        #pragma unroll
        for (int i = 0; i < 8; ++i)
            #pragma unroll
            for (int j = 0; j < 4; ++j) sf[i][j] = 0.0f;

        #pragma unroll
        for (int fk = 0; fk < 4; ++fk) {
            uint32_t kh[8][2], kl[8][2];
            #pragma unroll
            for (int p = 0; p < 4; ++p) {
                uint32_t r0[4], r1[4];
                const uint32_t ra = kst + (uint32_t)(p * 16) * AROWB + laneB + fk * 32;
                ldm_x4(r0, ra);
                ldm_x4(r1, ra + 9216);
                kh[p * 2 + 0][0] = r0[0]; kh[p * 2 + 0][1] = r0[1];
                kh[p * 2 + 1][0] = r0[2]; kh[p * 2 + 1][1] = r0[3];
                kl[p * 2 + 0][0] = r1[0]; kl[p * 2 + 0][1] = r1[1];
                kl[p * 2 + 1][0] = r1[2]; kl[p * 2 + 1][1] = r1[3];
            }
            #pragma unroll
            for (int nf = 0; nf < 8; ++nf) {
                mma16816(sf[nf], qh[fk], kh[nf]);
                mma16816(sf[nf], qh[fk], kl[nf]);
                mma16816(sf[nf], ql[fk], kh[nf]);
            }
        }

        float pmA = -1e30f, pmB = -1e30f;
        #pragma unroll
        for (int nf = 0; nf < 8; ++nf) {
            const float m0 = mb[nf * 8 + c0];
            const float m1 = mb[nf * 8 + c0 + 1];
            sf[nf][0] = fmaf(sf[nf][0], 0.125f, m0);
            sf[nf][1] = fmaf(sf[nf][1], 0.125f, m1);
            sf[nf][2] = fmaf(sf[nf][2], 0.125f, m0);
            sf[nf][3] = fmaf(sf[nf][3], 0.125f, m1);
            pmA = fmaxf(pmA, fmaxf(sf[nf][0], sf[nf][1]));
            pmB = fmaxf(pmB, fmaxf(sf[nf][2], sf[nf][3]));
        }
        pmA = fmaxf(pmA, __shfl_xor_sync(0xffffffffu, pmA, 1));
        pmA = fmaxf(pmA, __shfl_xor_sync(0xffffffffu, pmA, 2));
        pmB = fmaxf(pmB, __shfl_xor_sync(0xffffffffu, pmB, 1));
        pmB = fmaxf(pmB, __shfl_xor_sync(0xffffffffu, pmB, 2));
        const float mnA = fmaxf(mA, pmA), mnB = fmaxf(mB, pmB);
        const float alA = __expf(mA - mnA), alB = __expf(mB - mnB);
        mA = mnA; mB = mnB;
        float rsA = 0.0f, rsB = 0.0f;
        #pragma unroll
        for (int nf = 0; nf < 8; ++nf) {
            sf[nf][0] = __expf(sf[nf][0] - mnA);
            sf[nf][1] = __expf(sf[nf][1] - mnA);
            sf[nf][2] = __expf(sf[nf][2] - mnB);
            sf[nf][3] = __expf(sf[nf][3] - mnB);
            rsA += sf[nf][0] + sf[nf][1];
            rsB += sf[nf][2] + sf[nf][3];
        }
        rsA += __shfl_xor_sync(0xffffffffu, rsA, 1);
        rsA += __shfl_xor_sync(0xffffffffu, rsA, 2);
        rsB += __shfl_xor_sync(0xffffffffu, rsB, 1);
        rsB += __shfl_xor_sync(0xffffffffu, rsB, 2);
        lA = lA * alA + rsA;
        lB = lB * alB + rsB;
        #pragma unroll
        for (int nf = 0; nf < 8; ++nf) {
            of[nf][0] *= alA; of[nf][1] *= alA;
            of[nf][2] *= alB; of[nf][3] *= alB;
        }

        #pragma unroll
        for (int fk = 0; fk < 4; ++fk) {
            uint32_t aHi[4], aLo[4];
            bfsplit2(sf[2 * fk][0],     sf[2 * fk][1],     aHi[0], aLo[0]);
            bfsplit2(sf[2 * fk][2],     sf[2 * fk][3],     aHi[1], aLo[1]);
            bfsplit2(sf[2 * fk + 1][0], sf[2 * fk + 1][1], aHi[2], aLo[2]);
            bfsplit2(sf[2 * fk + 1][2], sf[2 * fk + 1][3], aHi[3], aLo[3]);
            uint32_t vh[8][2], vl[8][2];
            #pragma unroll
            for (int p = 0; p < 4; ++p) {
                uint32_t r0[4], r1[4];
                const uint32_t ra = kst + 18432 + (uint32_t)(p * 16) * AROWB + laneB + fk * 32;
                ldm_x4(r0, ra);
                ldm_x4(r1, ra + 9216);
                vh[p * 2 + 0][0] = r0[0]; vh[p * 2 + 0][1] = r0[1];
                vh[p * 2 + 1][0] = r0[2]; vh[p * 2 + 1][1] = r0[3];
                vl[p * 2 + 0][0] = r1[0]; vl[p * 2 + 0][1] = r1[1];
                vl[p * 2 + 1][0] = r1[2]; vl[p * 2 + 1][1] = r1[3];
            }
            #pragma unroll
            for (int nf = 0; nf < 8; ++nf) {
                mma16816(of[nf], aHi, vh[nf]);
                mma16816(of[nf], aHi, vl[nf]);
                mma16816(of[nf], aLo, vh[nf]);
            }
        }

        __syncthreads();
        if (tile + 2 < 32) LOADKV(tile + 2, s);
        cp_commit();
    }

    // write O as bf16 hi/lo (no fp32 Y)
    const float iA = 1.0f / lA, iB = 1.0f / lB;
    const int rA = lane >> 2;
    const int rowA = tokb + q0 + w * 16 + rA;
    #pragma unroll
    for (int nf = 0; nf < 8; ++nf) {
        const int col = colb + nf * 8 + c0;
        uint32_t h0, l0, h1, l1;
        bfsplit2(of[nf][0] * iA, of[nf][1] * iA, h0, l0);
        bfsplit2(of[nf][2] * iB, of[nf][3] * iB, h1, l1);
        *(uint32_t*)&Yhi[(size_t)rowA * 1024 + col]       = h0;
        *(uint32_t*)&Ylo[(size_t)rowA * 1024 + col]       = l0;
        *(uint32_t*)&Yhi[(size_t)(rowA + 8) * 1024 + col] = h1;
        *(uint32_t*)&Ylo[(size_t)(rowA + 8) * 1024 + col] = l1;
    }
}

// ---------------------------------------------------------------------------
// LayerNorm: one row per CTA; optional fused bf16 hi/lo split output
// ---------------------------------------------------------------------------
__global__ __launch_bounds__(256)
void ln_kernel(const float* __restrict__ X, const float* __restrict__ w,
               const float* __restrict__ b, float* __restrict__ out,
               unsigned short* __restrict__ hi, unsigned short* __restrict__ lo)
{
    __shared__ float red[2][8];
    const int t = threadIdx.x;
    const size_t row = blockIdx.x;
    float4 xv = *(const float4*)&X[row * 1024 + t * 4];
    float s  = xv.x + xv.y + xv.z + xv.w;
    float s2 = xv.x * xv.x + xv.y * xv.y + xv.z * xv.z + xv.w * xv.w;
    #pragma unroll
    for (int off = 16; off; off >>= 1) {
        s  += __shfl_xor_sync(0xffffffffu, s,  off);
        s2 += __shfl_xor_sync(0xffffffffu, s2, off);
    }
    if ((t & 31) == 0) { red[0][t >> 5] = s; red[1][t >> 5] = s2; }
    __syncthreads();
    float S = 0.0f, S2 = 0.0f;
    #pragma unroll
    for (int i = 0; i < 8; ++i) { S += red[0][i]; S2 += red[1][i]; }
    const float mean = S * (1.0f / 1024.0f);
    const float var  = S2 * (1.0f / 1024.0f) - mean * mean;
    const float rstd = rsqrtf(var + 1e-5f);
    float4 wv = *(const float4*)&w[t * 4];
    float4 bv = *(const float4*)&b[t * 4];
    float4 r;
    r.x = (xv.x - mean) * rstd * wv.x + bv.x;
    r.y = (xv.y - mean) * rstd * wv.y + bv.y;
    r.z = (xv.z - mean) * rstd * wv.z + bv.z;
    r.w = (xv.w - mean) * rstd * wv.w + bv.w;
    if (out) *(float4*)&out[row * 1024 + t * 4] = r;
    if (hi) {
        uint32_t h0, l0, h1, l1;
        bfsplit2(r.x, r.y, h0, l0);
        bfsplit2(r.z, r.w, h1, l1);
        uint2 hv = make_uint2(h0, h1), lv = make_uint2(l0, l1);
        *(uint2*)&hi[row * 1024 + t * 4] = hv;
        *(uint2*)&lo[row * 1024 + t * 4] = lv;
    }
}

// ---------------------------------------------------------------------------
// launch
// ---------------------------------------------------------------------------
extern "C" void kernel_launch(void* const* d_in, const int* in_sizes, int n_in,
                              void* d_out, int out_size)
{
    (void)in_sizes; (void)n_in; (void)out_size;
    const float* x    = (const float*)d_in[0];
    const int*   mask = (const int*)  d_in[1];
    const float* WQ   = (const float*)d_in[2];
    const float* bQ   = (const float*)d_in[3];
    const float* WK   = (const float*)d_in[4];
    const float* bK   = (const float*)d_in[5];
    const float* WV   = (const float*)d_in[6];
    const float* bV   = (const float*)d_in[7];
    const float* WY   = (const float*)d_in[8];
    const float* bY   = (const float*)d_in[9];
    const float* ln1w = (const float*)d_in[10];
    const float* ln1b = (const float*)d_in[11];
    const float* ln2w = (const float*)d_in[12];
    const float* ln2b = (const float*)d_in[13];
    const float* W1   = (const float*)d_in[14];
    const float* b1   = (const float*)d_in[15];
    const float* W2   = (const float*)d_in[16];
    const float* b2   = (const float*)d_in[17];
    float* out = (float*)d_out;

    float *Qp, *Kp, *Vp, *Yp;
    unsigned short *Ahi, *Alo, *Whi, *Wlo;
    unsigned short *Qhi, *Qlo, *Khi, *Klo, *Vthi, *Vtlo;
    cudaGetSymbolAddress((void**)&Qp,  g_Q);
    cudaGetSymbolAddress((void**)&Kp,  g_K);
    cudaGetSymbolAddress((void**)&Vp,  g_V);
    cudaGetSymbolAddress((void**)&Yp,  g_Y);
    cudaGetSymbolAddress((void**)&Ahi, g_Ahi);
    cudaGetSymbolAddress((void**)&Alo, g_Alo);
    cudaGetSymbolAddress((void**)&Whi, g_Whi);
    cudaGetSymbolAddress((void**)&Wlo, g_Wlo);
    cudaGetSymbolAddress((void**)&Qhi,  g_Qhi);
    cudaGetSymbolAddress((void**)&Qlo,  g_Qlo);
    cudaGetSymbolAddress((void**)&Khi,  g_Khi);
    cudaGetSymbolAddress((void**)&Klo,  g_Klo);
    cudaGetSymbolAddress((void**)&Vthi, g_Vthi);
    cudaGetSymbolAddress((void**)&Vtlo, g_Vtlo);

    // Yhi/Ylo live inside g_Y's 16MB
    unsigned short* Yhi = (unsigned short*)Yp;
    unsigned short* Ylo = (unsigned short*)Yp + (size_t)4096 * 1024;

    const size_t MB = (size_t)1024 * 1024;

    cudaFuncSetAttribute(tgemm_kernel<0>,
                         cudaFuncAttributeMaxDynamicSharedMemorySize, TG_SMEM);
    cudaFuncSetAttribute(tgemm_kernel<1>,
                         cudaFuncAttributeMaxDynamicSharedMemorySize, TG_SMEM);
    cudaFuncSetAttribute(tgemm_kernel<2>,
                         cudaFuncAttributeMaxDynamicSharedMemorySize, TG_SMEM);
    cudaFuncSetAttribute(attn_mma_kernel,
                         cudaFuncAttributeMaxDynamicSharedMemorySize, ATT_SMEM);

    dim3 blk(256);
    dim3 tsb(32, 8);

    // weight transposes: 4 D x D fused; W1; W2
    tsplit_kernel<<<dim3(32, 32, 4), tsb>>>(WQ, WK, WV, WY, Whi, Wlo, MB, 1024, 1024);
    tsplit_kernel<<<dim3(128, 32, 1), tsb>>>(W1, W1, W1, W1, Whi + 4 * MB, Wlo + 4 * MB,
                                             0, 1024, 4096);
    tsplit_kernel<<<dim3(32, 128, 1), tsb>>>(W2, W2, W2, W2, Whi + 8 * MB, Wlo + 8 * MB,
                                             0, 4096, 1024);

    // x split
    split_kernel<<<4096, blk>>>(x, Ahi, Alo, (4096 * 1024) / 4);

    // QKV: Q,K -> bf16 split directly; V -> fp32 (for transpose)
    tgemm_kernel<0><<<dim3(8, 32, 3), blk, TG_SMEM>>>(
        Ahi, Alo, Whi, Wlo, MB, bQ, bK, bV, nullptr,
        nullptr, nullptr, Vp,
        Qhi, Khi, nullptr,
        Qlo, Klo, nullptr,
        4096, 1024, 1024);

    // V transpose+split
    tsplit_kernel<<<dim3(32, 128, 1), tsb>>>(Vp, Vp, Vp, Vp, Vthi, Vtlo, 0, 4096, 1024);

    // attention -> Yhi/Ylo bf16
    attn_mma_kernel<<<dim3(16, 32), blk, ATT_SMEM>>>(
        Qhi, Qlo, Khi, Klo, Vthi, Vtlo, mask, Yhi, Ylo);

    // out-proj + residual x -> fp32 g_Q
    tgemm_kernel<2><<<dim3(8, 32, 1), blk, TG_SMEM>>>(
        Yhi, Ylo, Whi + 3 * MB, Wlo + 3 * MB, 0, bY, bY, bY, x,
        Qp, nullptr, nullptr,
        nullptr, nullptr, nullptr,
        nullptr, nullptr, nullptr,
        4096, 1024, 1024);

    // h = LN1 -> fp32 g_K + bf16 split (g_Qhi/g_Qlo reused)
    ln_kernel<<<4096, blk>>>(Qp, ln1w, ln1b, Kp, Qhi, Qlo);

    // FFN1: gelu(h@W1+b1) -> bf16 split only (g_Ahi/g_Alo reused)
    tgemm_kernel<1><<<dim3(32, 32, 1), blk, TG_SMEM>>>(
        Qhi, Qlo, Whi + 4 * MB, Wlo + 4 * MB, 0, b1, b1, b1, nullptr,
        nullptr, nullptr, nullptr,
        Ahi, nullptr, nullptr,
        Alo, nullptr, nullptr,
        4096, 4096, 1024);

    // FFN2: ff@W2+b2+h -> fp32 g_V
    tgemm_kernel<2><<<dim3(8, 32, 1), blk, TG_SMEM>>>(
        Ahi, Alo, Whi + 8 * MB, Wlo + 8 * MB, 0, b2, b2, b2, Kp,
        Vp, nullptr, nullptr,
        nullptr, nullptr, nullptr,
        nullptr, nullptr, nullptr,
        4096, 1024, 4096);

    // out = LN2 (fp32 only)
    ln_kernel<<<4096, blk>>>(Vp, ln2w, ln2b, out, nullptr, nullptr);
}